// round 1
// baseline (speedup 1.0000x reference)
#include <cuda_runtime.h>
#include <cstddef>

// ---------------------------------------------------------------------------
// TransformerEncoder baseline: fp32 SIMT pipeline.
// x[2,2048,1024] -> LN1 -> QKV -> attention(16 heads, hd=64, scale 1/32)
//   -> O proj + x -> LN2 -> MLP(4096, relu) -> relu -> + out1
// ---------------------------------------------------------------------------

#define FEATS  1024
#define SEQ    2048
#define BATCH  2
#define TOK    (BATCH * SEQ)     // 4096
#define HEADS  16
#define HD     64                // FEATS / HEADS
#define HIDDEN 4096
#define LN_EPS 1e-5f

// ---- scratch (device globals; no runtime allocation allowed) ----
__device__ float g_h1[(size_t)TOK * FEATS];
__device__ float g_q [(size_t)TOK * FEATS];
__device__ float g_k [(size_t)TOK * FEATS];
__device__ float g_v [(size_t)TOK * FEATS];
__device__ float g_scores[(size_t)BATCH * HEADS * SEQ * SEQ];   // 512 MB
__device__ float g_attn[(size_t)TOK * FEATS];
__device__ float g_out1[(size_t)TOK * FEATS];
__device__ float g_h2 [(size_t)TOK * FEATS];
__device__ float g_m1 [(size_t)TOK * HIDDEN];                   // 64 MB

// ---------------------------------------------------------------------------
// LayerNorm: one block per token (1024 feats), 256 threads, float4 per thread
// ---------------------------------------------------------------------------
__global__ void ln_kernel(const float* __restrict__ x,
                          const float* __restrict__ g,
                          const float* __restrict__ b,
                          float* __restrict__ out) {
    const size_t row = blockIdx.x;
    const int t = threadIdx.x;
    const float4* xr = reinterpret_cast<const float4*>(x + row * FEATS);
    float4 v = xr[t];

    float s  = v.x + v.y + v.z + v.w;
    float ss = v.x * v.x + v.y * v.y + v.z * v.z + v.w * v.w;

    __shared__ float smS[8], smQ[8];
    #pragma unroll
    for (int o = 16; o; o >>= 1) {
        s  += __shfl_xor_sync(0xffffffffu, s,  o);
        ss += __shfl_xor_sync(0xffffffffu, ss, o);
    }
    if ((t & 31) == 0) { smS[t >> 5] = s; smQ[t >> 5] = ss; }
    __syncthreads();
    float tS = 0.f, tQ = 0.f;
    #pragma unroll
    for (int i = 0; i < 8; i++) { tS += smS[i]; tQ += smQ[i]; }

    const float mean = tS * (1.0f / FEATS);
    const float var  = tQ * (1.0f / FEATS) - mean * mean;
    const float rstd = rsqrtf(var + LN_EPS);

    float4 gg = reinterpret_cast<const float4*>(g)[t];
    float4 bb = reinterpret_cast<const float4*>(b)[t];
    float4 o4;
    o4.x = (v.x - mean) * rstd * gg.x + bb.x;
    o4.y = (v.y - mean) * rstd * gg.y + bb.y;
    o4.z = (v.z - mean) * rstd * gg.z + bb.z;
    o4.w = (v.w - mean) * rstd * gg.w + bb.w;
    reinterpret_cast<float4*>(out + row * FEATS)[t] = o4;
}

// ---------------------------------------------------------------------------
// Softmax over rows of length SEQ=2048. One block per row, 256 threads,
// 8 floats/thread held in registers.
// ---------------------------------------------------------------------------
__global__ void softmax_kernel(float* __restrict__ S) {
    const size_t row = blockIdx.x;
    float* p = S + row * (size_t)SEQ;
    const int t = threadIdx.x;

    float4 a = reinterpret_cast<float4*>(p)[t];
    float4 b = reinterpret_cast<float4*>(p)[t + 256];

    float m = fmaxf(fmaxf(fmaxf(a.x, a.y), fmaxf(a.z, a.w)),
                    fmaxf(fmaxf(b.x, b.y), fmaxf(b.z, b.w)));
    __shared__ float sm[8];
    #pragma unroll
    for (int o = 16; o; o >>= 1) m = fmaxf(m, __shfl_xor_sync(0xffffffffu, m, o));
    if ((t & 31) == 0) sm[t >> 5] = m;
    __syncthreads();
    float mm = sm[0];
    #pragma unroll
    for (int i = 1; i < 8; i++) mm = fmaxf(mm, sm[i]);
    __syncthreads();   // before sm reuse

    a.x = __expf(a.x - mm); a.y = __expf(a.y - mm);
    a.z = __expf(a.z - mm); a.w = __expf(a.w - mm);
    b.x = __expf(b.x - mm); b.y = __expf(b.y - mm);
    b.z = __expf(b.z - mm); b.w = __expf(b.w - mm);

    float s = a.x + a.y + a.z + a.w + b.x + b.y + b.z + b.w;
    #pragma unroll
    for (int o = 16; o; o >>= 1) s += __shfl_xor_sync(0xffffffffu, s, o);
    if ((t & 31) == 0) sm[t >> 5] = s;
    __syncthreads();
    float tot = 0.f;
    #pragma unroll
    for (int i = 0; i < 8; i++) tot += sm[i];
    const float inv = __fdividef(1.0f, tot);

    a.x *= inv; a.y *= inv; a.z *= inv; a.w *= inv;
    b.x *= inv; b.y *= inv; b.z *= inv; b.w *= inv;
    reinterpret_cast<float4*>(p)[t]       = a;
    reinterpret_cast<float4*>(p)[t + 256] = b;
}

// ---------------------------------------------------------------------------
// Tiled GEMM.  C[m,n] = alpha * sum_k A(m,k) * B(n,k)   (TRANSB = true, "NT")
//              C[m,n] = alpha * sum_k A(m,k) * B(k,n)   (TRANSB = false, "NN")
// Epilogue: EPI 0=none, 1=relu, 2=+res, 3=relu then +res.  bias optional.
// Batch offsets: z-block -> (bb = z/H, hh = z%H); ptr += bb*s?b + hh*s?h.
// All dims assumed multiples of tile sizes (true for this problem).
// ---------------------------------------------------------------------------
template<int BM, int BN, int BK, int TM, int TN, bool TRANSB, int EPI>
__global__ void __launch_bounds__((BM / TM) * (BN / TN))
gemm_kernel(const float* __restrict__ A, const float* __restrict__ B,
            float* __restrict__ C, const float* __restrict__ bias,
            const float* __restrict__ res,
            int K, int lda, int ldb, int ldc,
            long long sAb, long long sAh, long long sBb, long long sBh,
            long long sCb, long long sCh, int H, float alpha) {
    constexpr int NT = (BM / TM) * (BN / TN);

    const int bz = blockIdx.z;
    const int bb = bz / H;
    const int hh = bz - bb * H;
    A += (size_t)bb * sAb + (size_t)hh * sAh;
    B += (size_t)bb * sBb + (size_t)hh * sBh;
    C += (size_t)bb * sCb + (size_t)hh * sCh;
    const float* R = res ? res + (size_t)bb * sCb + (size_t)hh * sCh : nullptr;

    const int m0 = blockIdx.y * BM;
    const int n0 = blockIdx.x * BN;

    __shared__ float As[BK][BM + 4];
    __shared__ float Bs[BK][BN + 4];

    const int tid = threadIdx.x;
    const int tx  = tid % (BN / TN);
    const int ty  = tid / (BN / TN);

    float acc[TM][TN];
    #pragma unroll
    for (int i = 0; i < TM; i++)
        #pragma unroll
        for (int j = 0; j < TN; j++) acc[i][j] = 0.f;

    for (int k0 = 0; k0 < K; k0 += BK) {
        // --- load A tile (BM x BK), store transposed into As[k][m] ---
        #pragma unroll
        for (int i = 0; i < BM * BK / 4 / NT; i++) {
            int id = tid + i * NT;
            int r  = id / (BK / 4);
            int c  = (id % (BK / 4)) * 4;
            float4 v = *reinterpret_cast<const float4*>(
                &A[(size_t)(m0 + r) * lda + k0 + c]);
            As[c + 0][r] = v.x; As[c + 1][r] = v.y;
            As[c + 2][r] = v.z; As[c + 3][r] = v.w;
        }
        // --- load B tile ---
        if (TRANSB) {
            #pragma unroll
            for (int i = 0; i < BN * BK / 4 / NT; i++) {
                int id = tid + i * NT;
                int r  = id / (BK / 4);
                int c  = (id % (BK / 4)) * 4;
                float4 v = *reinterpret_cast<const float4*>(
                    &B[(size_t)(n0 + r) * ldb + k0 + c]);
                Bs[c + 0][r] = v.x; Bs[c + 1][r] = v.y;
                Bs[c + 2][r] = v.z; Bs[c + 3][r] = v.w;
            }
        } else {
            #pragma unroll
            for (int i = 0; i < BN * BK / 4 / NT; i++) {
                int id = tid + i * NT;
                int r  = id / (BN / 4);
                int c  = (id % (BN / 4)) * 4;
                float4 v = *reinterpret_cast<const float4*>(
                    &B[(size_t)(k0 + r) * ldb + n0 + c]);
                *reinterpret_cast<float4*>(&Bs[r][c]) = v;
            }
        }
        __syncthreads();

        #pragma unroll
        for (int kk = 0; kk < BK; kk++) {
            float a[TM], bf[TN];
            #pragma unroll
            for (int h = 0; h < TM / 4; h++) {
                float4 t4 = *reinterpret_cast<const float4*>(
                    &As[kk][h * (BM / 2) + ty * 4]);
                a[4 * h + 0] = t4.x; a[4 * h + 1] = t4.y;
                a[4 * h + 2] = t4.z; a[4 * h + 3] = t4.w;
            }
            #pragma unroll
            for (int h = 0; h < TN / 4; h++) {
                float4 t4 = *reinterpret_cast<const float4*>(
                    &Bs[kk][h * (BN / 2) + tx * 4]);
                bf[4 * h + 0] = t4.x; bf[4 * h + 1] = t4.y;
                bf[4 * h + 2] = t4.z; bf[4 * h + 3] = t4.w;
            }
            #pragma unroll
            for (int i = 0; i < TM; i++)
                #pragma unroll
                for (int j = 0; j < TN; j++)
                    acc[i][j] = fmaf(a[i], bf[j], acc[i][j]);
        }
        __syncthreads();
    }

    // --- epilogue ---
    #pragma unroll
    for (int im = 0; im < TM; im++) {
        int r = m0 + (im / 4) * (BM / 2) + ty * 4 + (im % 4);
        #pragma unroll
        for (int g = 0; g < TN / 4; g++) {
            int c = n0 + g * (BN / 2) + tx * 4;
            float4 v;
            v.x = acc[im][g * 4 + 0] * alpha;
            v.y = acc[im][g * 4 + 1] * alpha;
            v.z = acc[im][g * 4 + 2] * alpha;
            v.w = acc[im][g * 4 + 3] * alpha;
            if (bias) {
                float4 b4 = *reinterpret_cast<const float4*>(&bias[c]);
                v.x += b4.x; v.y += b4.y; v.z += b4.z; v.w += b4.w;
            }
            if (EPI == 1 || EPI == 3) {
                v.x = fmaxf(v.x, 0.f); v.y = fmaxf(v.y, 0.f);
                v.z = fmaxf(v.z, 0.f); v.w = fmaxf(v.w, 0.f);
            }
            if (EPI == 2 || EPI == 3) {
                float4 r4 = *reinterpret_cast<const float4*>(
                    &R[(size_t)r * ldc + c]);
                v.x += r4.x; v.y += r4.y; v.z += r4.z; v.w += r4.w;
            }
            *reinterpret_cast<float4*>(&C[(size_t)r * ldc + c]) = v;
        }
    }
}

// ---------------------------------------------------------------------------
extern "C" void kernel_launch(void* const* d_in, const int* in_sizes, int n_in,
                              void* d_out, int out_size) {
    (void)in_sizes; (void)n_in; (void)out_size;
    const float* x    = (const float*)d_in[0];
    const float* ln1g = (const float*)d_in[1];
    const float* ln1b = (const float*)d_in[2];
    const float* wq   = (const float*)d_in[3];
    const float* bq   = (const float*)d_in[4];
    const float* wk   = (const float*)d_in[5];
    const float* bk   = (const float*)d_in[6];
    const float* wv   = (const float*)d_in[7];
    const float* bv   = (const float*)d_in[8];
    const float* wo   = (const float*)d_in[9];
    const float* bo   = (const float*)d_in[10];
    const float* ln2g = (const float*)d_in[11];
    const float* ln2b = (const float*)d_in[12];
    const float* w1   = (const float*)d_in[13];
    const float* b1   = (const float*)d_in[14];
    const float* w2   = (const float*)d_in[15];
    const float* b2   = (const float*)d_in[16];
    float* out = (float*)d_out;

    float *h1, *q, *k, *v, *sc, *attn, *out1, *h2, *m1;
    cudaGetSymbolAddress((void**)&h1,   g_h1);
    cudaGetSymbolAddress((void**)&q,    g_q);
    cudaGetSymbolAddress((void**)&k,    g_k);
    cudaGetSymbolAddress((void**)&v,    g_v);
    cudaGetSymbolAddress((void**)&sc,   g_scores);
    cudaGetSymbolAddress((void**)&attn, g_attn);
    cudaGetSymbolAddress((void**)&out1, g_out1);
    cudaGetSymbolAddress((void**)&h2,   g_h2);
    cudaGetSymbolAddress((void**)&m1,   g_m1);

    // 1) LN1
    ln_kernel<<<TOK, 256>>>(x, ln1g, ln1b, h1);

    // 2) Q/K/V projections: [4096,1024] @ [1024,1024]^T + bias
    {
        dim3 grid(FEATS / 128, TOK / 128, 1);
        gemm_kernel<128,128,16,8,8,true,0><<<grid, 256>>>(
            h1, wq, q, bq, nullptr, FEATS, FEATS, FEATS, FEATS,
            0,0,0,0,0,0, 1, 1.0f);
        gemm_kernel<128,128,16,8,8,true,0><<<grid, 256>>>(
            h1, wk, k, bk, nullptr, FEATS, FEATS, FEATS, FEATS,
            0,0,0,0,0,0, 1, 1.0f);
        gemm_kernel<128,128,16,8,8,true,0><<<grid, 256>>>(
            h1, wv, v, bv, nullptr, FEATS, FEATS, FEATS, FEATS,
            0,0,0,0,0,0, 1, 1.0f);
    }

    // 3) scores[b,h] = Q_bh @ K_bh^T / 32   (batched over 32 (b,h) pairs)
    {
        dim3 grid(SEQ / 128, SEQ / 128, BATCH * HEADS);
        gemm_kernel<128,128,16,8,8,true,0><<<grid, 256>>>(
            q, k, sc, nullptr, nullptr,
            HD, FEATS, FEATS, SEQ,
            (long long)SEQ * FEATS, HD,
            (long long)SEQ * FEATS, HD,
            (long long)HEADS * SEQ * SEQ, (long long)SEQ * SEQ,
            HEADS, 1.0f / 32.0f);
    }

    // 4) softmax rows
    softmax_kernel<<<BATCH * HEADS * SEQ, 256>>>(sc);

    // 5) attn[b,i,h*64+d] = P_bh @ V_bh   (NN, N=64)
    {
        dim3 grid(HD / 64, SEQ / 128, BATCH * HEADS);
        gemm_kernel<128,64,16,8,4,false,0><<<grid, 256>>>(
            sc, v, attn, nullptr, nullptr,
            SEQ, SEQ, FEATS, FEATS,
            (long long)HEADS * SEQ * SEQ, (long long)SEQ * SEQ,
            (long long)SEQ * FEATS, HD,
            (long long)SEQ * FEATS, HD,
            HEADS, 1.0f);
    }

    // 6) O projection + residual x -> out1
    {
        dim3 grid(FEATS / 128, TOK / 128, 1);
        gemm_kernel<128,128,16,8,8,true,2><<<grid, 256>>>(
            attn, wo, out1, bo, x, FEATS, FEATS, FEATS, FEATS,
            0,0,0,0,0,0, 1, 1.0f);
    }

    // 7) LN2
    ln_kernel<<<TOK, 256>>>(out1, ln2g, ln2b, h2);

    // 8) MLP up: relu(h2 @ w1^T + b1) -> m1  [4096,4096]
    {
        dim3 grid(HIDDEN / 128, TOK / 128, 1);
        gemm_kernel<128,128,16,8,8,true,1><<<grid, 256>>>(
            h2, w1, m1, b1, nullptr, FEATS, FEATS, FEATS, HIDDEN,
            0,0,0,0,0,0, 1, 1.0f);
    }

    // 9) MLP down: relu(m1 @ w2^T + b2) + out1 -> out
    {
        dim3 grid(FEATS / 128, TOK / 128, 1);
        gemm_kernel<128,128,16,8,8,true,3><<<grid, 256>>>(
            m1, w2, out, b2, out1, HIDDEN, HIDDEN, HIDDEN, FEATS,
            0,0,0,0,0,0, 1, 1.0f);
    }
}

// round 2
// speedup vs baseline: 2.0310x; 2.0310x over previous
#include <cuda_runtime.h>
#include <cstdint>
#include <cstddef>

// ---------------------------------------------------------------------------
// TransformerEncoder: TF32 tensor-core pipeline (mma.sync.m16n8k8).
// ---------------------------------------------------------------------------

#define FEATS  1024
#define SEQ    2048
#define BATCH  2
#define TOK    (BATCH * SEQ)     // 4096
#define HEADS  16
#define HD     64
#define HIDDEN 4096
#define LN_EPS 1e-5f
#define BK     32

// ---- scratch ----
__device__ float g_h1[(size_t)TOK * FEATS];
__device__ float g_q [(size_t)TOK * FEATS];
__device__ float g_k [(size_t)TOK * FEATS];
__device__ float g_v [(size_t)TOK * FEATS];
__device__ float g_scores[(size_t)BATCH * HEADS * SEQ * SEQ];   // 512 MB
__device__ float g_attn[(size_t)TOK * FEATS];
__device__ float g_out1[(size_t)TOK * FEATS];
__device__ float g_h2 [(size_t)TOK * FEATS];
__device__ float g_m1 [(size_t)TOK * HIDDEN];

// ---------------------------------------------------------------------------
__device__ __forceinline__ float f2tf32(float x) {
    uint32_t u;
    asm("cvt.rna.tf32.f32 %0, %1;" : "=r"(u) : "f"(x));
    return __uint_as_float(u);
}

__device__ __forceinline__ void mma_tf32(float c[4],
                                         uint32_t a0, uint32_t a1,
                                         uint32_t a2, uint32_t a3,
                                         uint32_t b0, uint32_t b1) {
    asm volatile(
        "mma.sync.aligned.m16n8k8.row.col.f32.tf32.tf32.f32 "
        "{%0,%1,%2,%3}, {%4,%5,%6,%7}, {%8,%9}, {%0,%1,%2,%3};\n"
        : "+f"(c[0]), "+f"(c[1]), "+f"(c[2]), "+f"(c[3])
        : "r"(a0), "r"(a1), "r"(a2), "r"(a3), "r"(b0), "r"(b1));
}

// ---------------------------------------------------------------------------
// LayerNorm: one block per token, 256 threads, float4 per thread.
// ---------------------------------------------------------------------------
__global__ void ln_kernel(const float* __restrict__ x,
                          const float* __restrict__ g,
                          const float* __restrict__ b,
                          float* __restrict__ out) {
    const size_t row = blockIdx.x;
    const int t = threadIdx.x;
    float4 v = reinterpret_cast<const float4*>(x + row * FEATS)[t];

    float s  = v.x + v.y + v.z + v.w;
    float ss = v.x * v.x + v.y * v.y + v.z * v.z + v.w * v.w;

    __shared__ float smS[8], smQ[8];
    #pragma unroll
    for (int o = 16; o; o >>= 1) {
        s  += __shfl_xor_sync(0xffffffffu, s,  o);
        ss += __shfl_xor_sync(0xffffffffu, ss, o);
    }
    if ((t & 31) == 0) { smS[t >> 5] = s; smQ[t >> 5] = ss; }
    __syncthreads();
    float tS = 0.f, tQ = 0.f;
    #pragma unroll
    for (int i = 0; i < 8; i++) { tS += smS[i]; tQ += smQ[i]; }

    const float mean = tS * (1.0f / FEATS);
    const float var  = tQ * (1.0f / FEATS) - mean * mean;
    const float rstd = rsqrtf(var + LN_EPS);

    float4 gg = reinterpret_cast<const float4*>(g)[t];
    float4 bb = reinterpret_cast<const float4*>(b)[t];
    float4 o4;
    o4.x = (v.x - mean) * rstd * gg.x + bb.x;
    o4.y = (v.y - mean) * rstd * gg.y + bb.y;
    o4.z = (v.z - mean) * rstd * gg.z + bb.z;
    o4.w = (v.w - mean) * rstd * gg.w + bb.w;
    reinterpret_cast<float4*>(out + row * FEATS)[t] = o4;
}

// ---------------------------------------------------------------------------
// Softmax over rows of length SEQ. One block per row, 256 threads.
// ---------------------------------------------------------------------------
__global__ void softmax_kernel(float* __restrict__ S) {
    const size_t row = blockIdx.x;
    float* p = S + row * (size_t)SEQ;
    const int t = threadIdx.x;

    float4 a = reinterpret_cast<float4*>(p)[t];
    float4 b = reinterpret_cast<float4*>(p)[t + 256];

    float m = fmaxf(fmaxf(fmaxf(a.x, a.y), fmaxf(a.z, a.w)),
                    fmaxf(fmaxf(b.x, b.y), fmaxf(b.z, b.w)));
    __shared__ float sm[8];
    #pragma unroll
    for (int o = 16; o; o >>= 1) m = fmaxf(m, __shfl_xor_sync(0xffffffffu, m, o));
    if ((t & 31) == 0) sm[t >> 5] = m;
    __syncthreads();
    float mm = sm[0];
    #pragma unroll
    for (int i = 1; i < 8; i++) mm = fmaxf(mm, sm[i]);
    __syncthreads();

    a.x = __expf(a.x - mm); a.y = __expf(a.y - mm);
    a.z = __expf(a.z - mm); a.w = __expf(a.w - mm);
    b.x = __expf(b.x - mm); b.y = __expf(b.y - mm);
    b.z = __expf(b.z - mm); b.w = __expf(b.w - mm);

    float s = a.x + a.y + a.z + a.w + b.x + b.y + b.z + b.w;
    #pragma unroll
    for (int o = 16; o; o >>= 1) s += __shfl_xor_sync(0xffffffffu, s, o);
    if ((t & 31) == 0) sm[t >> 5] = s;
    __syncthreads();
    float tot = 0.f;
    #pragma unroll
    for (int i = 0; i < 8; i++) tot += sm[i];
    const float inv = __fdividef(1.0f, tot);

    a.x *= inv; a.y *= inv; a.z *= inv; a.w *= inv;
    b.x *= inv; b.y *= inv; b.z *= inv; b.w *= inv;
    reinterpret_cast<float4*>(p)[t]       = a;
    reinterpret_cast<float4*>(p)[t + 256] = b;
}

// ---------------------------------------------------------------------------
// TF32 tensor-core GEMM.
//   TRANSB=1: C[m,n] = alpha * sum_k A[m,k] * B[n,k]  (B row-major [N,K])
//   TRANSB=0: C[m,n] = alpha * sum_k A[m,k] * B[k,n]  (B row-major [K,N])
// 8 warps, warp tile WM x WN of m16n8k8 atoms. 256 threads.
// EPI: 0=none, 1=relu, 2=+res, 3=relu then +res. bias optional.
// Dims assumed multiples of tile sizes.
// Smem bank layout: As[m][k] stride BK+4=36 (=4 mod 32) -> conflict-free
// fragment loads (banks 4*(lane/4)+lane%4 distinct). NT Bs same. NN Bs[k][n]
// stride BN+8 (=8 mod 32) -> banks 8*(lane%4)+lane/4 distinct.
// ---------------------------------------------------------------------------
template<int BM, int BN, int WM, int WN, bool TRANSB, int EPI>
__global__ void __launch_bounds__(256)
mma_gemm(const float* __restrict__ A, const float* __restrict__ B,
         float* __restrict__ C, const float* __restrict__ bias,
         const float* __restrict__ res,
         int K, int lda, int ldb, int ldc,
         long long sAb, long long sAh, long long sBb, long long sBh,
         long long sCb, long long sCh, int H, float alpha) {
    constexpr int M_AT = WM / 16;
    constexpr int N_AT = WN / 8;
    constexpr int WARPS_N = BN / WN;
    constexpr int AS_LD = BK + 4;                       // 36
    constexpr int BS_LD = TRANSB ? (BK + 4) : (BN + 8); // 36 / BN+8

    const int bz = blockIdx.z;
    const int bb = bz / H;
    const int hh = bz - bb * H;
    A += (size_t)bb * sAb + (size_t)hh * sAh;
    B += (size_t)bb * sBb + (size_t)hh * sBh;
    C += (size_t)bb * sCb + (size_t)hh * sCh;
    const float* R = res ? res + (size_t)bb * sCb + (size_t)hh * sCh : nullptr;

    const int m0 = blockIdx.y * BM;
    const int n0 = blockIdx.x * BN;

    __shared__ float As[BM * AS_LD];
    __shared__ float Bs[(TRANSB ? BN : BK) * BS_LD];

    const int tid  = threadIdx.x;
    const int wid  = tid >> 5;
    const int lane = tid & 31;
    const int lq   = lane >> 2;   // 0..7
    const int lr   = lane & 3;    // 0..3
    const int wm   = wid / WARPS_N;
    const int wn   = wid % WARPS_N;

    float acc[M_AT][N_AT][4];
    #pragma unroll
    for (int i = 0; i < M_AT; i++)
        #pragma unroll
        for (int j = 0; j < N_AT; j++)
            #pragma unroll
            for (int r = 0; r < 4; r++) acc[i][j][r] = 0.f;

    for (int k0 = 0; k0 < K; k0 += BK) {
        // ---- stage A (BM x BK), row-major, cvt to tf32 ----
        #pragma unroll
        for (int i = 0; i < BM / 32; i++) {
            int id = tid + i * 256;
            int r  = id >> 3;            // /(BK/4)
            int c  = (id & 7) << 2;
            float4 v = *reinterpret_cast<const float4*>(
                &A[(size_t)(m0 + r) * lda + k0 + c]);
            v.x = f2tf32(v.x); v.y = f2tf32(v.y);
            v.z = f2tf32(v.z); v.w = f2tf32(v.w);
            *reinterpret_cast<float4*>(&As[r * AS_LD + c]) = v;
        }
        // ---- stage B ----
        if (TRANSB) {
            #pragma unroll
            for (int i = 0; i < BN / 32; i++) {
                int id = tid + i * 256;
                int r  = id >> 3;
                int c  = (id & 7) << 2;
                float4 v = *reinterpret_cast<const float4*>(
                    &B[(size_t)(n0 + r) * ldb + k0 + c]);
                v.x = f2tf32(v.x); v.y = f2tf32(v.y);
                v.z = f2tf32(v.z); v.w = f2tf32(v.w);
                *reinterpret_cast<float4*>(&Bs[r * BS_LD + c]) = v;
            }
        } else {
            #pragma unroll
            for (int i = 0; i < BN / 32; i++) {
                int id = tid + i * 256;
                int r  = id / (BN / 4);
                int c  = (id % (BN / 4)) << 2;
                float4 v = *reinterpret_cast<const float4*>(
                    &B[(size_t)(k0 + r) * ldb + n0 + c]);
                v.x = f2tf32(v.x); v.y = f2tf32(v.y);
                v.z = f2tf32(v.z); v.w = f2tf32(v.w);
                *reinterpret_cast<float4*>(&Bs[r * BS_LD + c]) = v;
            }
        }
        __syncthreads();

        // ---- math: 4 k8 chunks ----
        #pragma unroll
        for (int kk = 0; kk < 4; kk++) {
            const int kb = kk * 8;
            uint32_t af[M_AT][4];
            #pragma unroll
            for (int mi = 0; mi < M_AT; mi++) {
                const int m = wm * WM + mi * 16 + lq;
                af[mi][0] = __float_as_uint(As[(m     ) * AS_LD + kb + lr    ]);
                af[mi][1] = __float_as_uint(As[(m + 8 ) * AS_LD + kb + lr    ]);
                af[mi][2] = __float_as_uint(As[(m     ) * AS_LD + kb + lr + 4]);
                af[mi][3] = __float_as_uint(As[(m + 8 ) * AS_LD + kb + lr + 4]);
            }
            uint32_t bf[N_AT][2];
            #pragma unroll
            for (int ni = 0; ni < N_AT; ni++) {
                const int n = wn * WN + ni * 8 + lq;
                if (TRANSB) {
                    bf[ni][0] = __float_as_uint(Bs[n * BS_LD + kb + lr    ]);
                    bf[ni][1] = __float_as_uint(Bs[n * BS_LD + kb + lr + 4]);
                } else {
                    bf[ni][0] = __float_as_uint(Bs[(kb + lr    ) * BS_LD + n]);
                    bf[ni][1] = __float_as_uint(Bs[(kb + lr + 4) * BS_LD + n]);
                }
            }
            #pragma unroll
            for (int mi = 0; mi < M_AT; mi++)
                #pragma unroll
                for (int ni = 0; ni < N_AT; ni++)
                    mma_tf32(acc[mi][ni], af[mi][0], af[mi][1], af[mi][2],
                             af[mi][3], bf[ni][0], bf[ni][1]);
        }
        __syncthreads();
    }

    // ---- epilogue ----
    #pragma unroll
    for (int mi = 0; mi < M_AT; mi++) {
        #pragma unroll
        for (int ni = 0; ni < N_AT; ni++) {
            const int r = m0 + wm * WM + mi * 16 + lq;
            const int c = n0 + wn * WN + ni * 8 + lr * 2;
            float2 v0, v1;
            v0.x = acc[mi][ni][0] * alpha; v0.y = acc[mi][ni][1] * alpha;
            v1.x = acc[mi][ni][2] * alpha; v1.y = acc[mi][ni][3] * alpha;
            if (bias) {
                float2 b2 = *reinterpret_cast<const float2*>(&bias[c]);
                v0.x += b2.x; v0.y += b2.y;
                v1.x += b2.x; v1.y += b2.y;
            }
            if (EPI == 1 || EPI == 3) {
                v0.x = fmaxf(v0.x, 0.f); v0.y = fmaxf(v0.y, 0.f);
                v1.x = fmaxf(v1.x, 0.f); v1.y = fmaxf(v1.y, 0.f);
            }
            if (EPI == 2 || EPI == 3) {
                float2 r0 = *reinterpret_cast<const float2*>(
                    &R[(size_t)r * ldc + c]);
                float2 r1 = *reinterpret_cast<const float2*>(
                    &R[(size_t)(r + 8) * ldc + c]);
                v0.x += r0.x; v0.y += r0.y;
                v1.x += r1.x; v1.y += r1.y;
            }
            *reinterpret_cast<float2*>(&C[(size_t)r * ldc + c])       = v0;
            *reinterpret_cast<float2*>(&C[(size_t)(r + 8) * ldc + c]) = v1;
        }
    }
}

// ---------------------------------------------------------------------------
extern "C" void kernel_launch(void* const* d_in, const int* in_sizes, int n_in,
                              void* d_out, int out_size) {
    (void)in_sizes; (void)n_in; (void)out_size;
    const float* x    = (const float*)d_in[0];
    const float* ln1g = (const float*)d_in[1];
    const float* ln1b = (const float*)d_in[2];
    const float* wq   = (const float*)d_in[3];
    const float* bq   = (const float*)d_in[4];
    const float* wk   = (const float*)d_in[5];
    const float* bk   = (const float*)d_in[6];
    const float* wv   = (const float*)d_in[7];
    const float* bv   = (const float*)d_in[8];
    const float* wo   = (const float*)d_in[9];
    const float* bo   = (const float*)d_in[10];
    const float* ln2g = (const float*)d_in[11];
    const float* ln2b = (const float*)d_in[12];
    const float* w1   = (const float*)d_in[13];
    const float* b1   = (const float*)d_in[14];
    const float* w2   = (const float*)d_in[15];
    const float* b2   = (const float*)d_in[16];
    float* out = (float*)d_out;

    float *h1, *q, *k, *v, *sc, *attn, *out1, *h2, *m1;
    cudaGetSymbolAddress((void**)&h1,   g_h1);
    cudaGetSymbolAddress((void**)&q,    g_q);
    cudaGetSymbolAddress((void**)&k,    g_k);
    cudaGetSymbolAddress((void**)&v,    g_v);
    cudaGetSymbolAddress((void**)&sc,   g_scores);
    cudaGetSymbolAddress((void**)&attn, g_attn);
    cudaGetSymbolAddress((void**)&out1, g_out1);
    cudaGetSymbolAddress((void**)&h2,   g_h2);
    cudaGetSymbolAddress((void**)&m1,   g_m1);

    // 1) LN1
    ln_kernel<<<TOK, 256>>>(x, ln1g, ln1b, h1);

    // 2) Q/K/V projections: [4096,1024] x [1024,1024]^T + bias
    {
        dim3 grid(FEATS / 128, TOK / 128, 1);
        mma_gemm<128,128,64,32,true,0><<<grid, 256>>>(
            h1, wq, q, bq, nullptr, FEATS, FEATS, FEATS, FEATS,
            0,0,0,0,0,0, 1, 1.0f);
        mma_gemm<128,128,64,32,true,0><<<grid, 256>>>(
            h1, wk, k, bk, nullptr, FEATS, FEATS, FEATS, FEATS,
            0,0,0,0,0,0, 1, 1.0f);
        mma_gemm<128,128,64,32,true,0><<<grid, 256>>>(
            h1, wv, v, bv, nullptr, FEATS, FEATS, FEATS, FEATS,
            0,0,0,0,0,0, 1, 1.0f);
    }

    // 3) scores[b,h] = Q_bh @ K_bh^T / 32
    {
        dim3 grid(SEQ / 128, SEQ / 128, BATCH * HEADS);
        mma_gemm<128,128,64,32,true,0><<<grid, 256>>>(
            q, k, sc, nullptr, nullptr,
            HD, FEATS, FEATS, SEQ,
            (long long)SEQ * FEATS, HD,
            (long long)SEQ * FEATS, HD,
            (long long)HEADS * SEQ * SEQ, (long long)SEQ * SEQ,
            HEADS, 1.0f / 32.0f);
    }

    // 4) softmax
    softmax_kernel<<<BATCH * HEADS * SEQ, 256>>>(sc);

    // 5) attn = P @ V  (NN, N=64 per head)
    {
        dim3 grid(1, SEQ / 128, BATCH * HEADS);
        mma_gemm<128,64,32,32,false,0><<<grid, 256>>>(
            sc, v, attn, nullptr, nullptr,
            SEQ, SEQ, FEATS, FEATS,
            (long long)HEADS * SEQ * SEQ, (long long)SEQ * SEQ,
            (long long)SEQ * FEATS, HD,
            (long long)SEQ * FEATS, HD,
            HEADS, 1.0f);
    }

    // 6) O projection + residual
    {
        dim3 grid(FEATS / 128, TOK / 128, 1);
        mma_gemm<128,128,64,32,true,2><<<grid, 256>>>(
            attn, wo, out1, bo, x, FEATS, FEATS, FEATS, FEATS,
            0,0,0,0,0,0, 1, 1.0f);
    }

    // 7) LN2
    ln_kernel<<<TOK, 256>>>(out1, ln2g, ln2b, h2);

    // 8) MLP up: relu(h2 @ w1^T + b1)
    {
        dim3 grid(HIDDEN / 128, TOK / 128, 1);
        mma_gemm<128,128,64,32,true,1><<<grid, 256>>>(
            h2, w1, m1, b1, nullptr, FEATS, FEATS, FEATS, HIDDEN,
            0,0,0,0,0,0, 1, 1.0f);
    }

    // 9) MLP down: relu(m1 @ w2^T + b2) + out1
    {
        dim3 grid(FEATS / 128, TOK / 128, 1);
        mma_gemm<128,128,64,32,true,3><<<grid, 256>>>(
            m1, w2, out, b2, out1, HIDDEN, HIDDEN, HIDDEN, FEATS,
            0,0,0,0,0,0, 1, 1.0f);
    }
}

// round 3
// speedup vs baseline: 2.8303x; 1.3936x over previous
#include <cuda_runtime.h>
#include <cstdint>
#include <cstddef>

#define FEATS  1024
#define SEQ    2048
#define BATCH  2
#define TOK    (BATCH * SEQ)     // 4096
#define HEADS  16
#define HD     64
#define HIDDEN 4096
#define LN_EPS 1e-5f
#define BK     32

// ---- scratch ----
__device__ float g_h1[(size_t)TOK * FEATS];
__device__ float g_q [(size_t)TOK * FEATS];
__device__ float g_k [(size_t)TOK * FEATS];
__device__ float g_v [(size_t)TOK * FEATS];
__device__ float g_attn[(size_t)TOK * FEATS];
__device__ float g_out1[(size_t)TOK * FEATS];
__device__ float g_h2 [(size_t)TOK * FEATS];
__device__ float g_m1 [(size_t)TOK * HIDDEN];

// ---------------------------------------------------------------------------
__device__ __forceinline__ float f2tf32(float x) {
    uint32_t u;
    asm("cvt.rna.tf32.f32 %0, %1;" : "=r"(u) : "f"(x));
    return __uint_as_float(u);
}

__device__ __forceinline__ void mma_tf32(float c[4],
                                         uint32_t a0, uint32_t a1,
                                         uint32_t a2, uint32_t a3,
                                         uint32_t b0, uint32_t b1) {
    asm volatile(
        "mma.sync.aligned.m16n8k8.row.col.f32.tf32.tf32.f32 "
        "{%0,%1,%2,%3}, {%4,%5,%6,%7}, {%8,%9}, {%0,%1,%2,%3};\n"
        : "+f"(c[0]), "+f"(c[1]), "+f"(c[2]), "+f"(c[3])
        : "r"(a0), "r"(a1), "r"(a2), "r"(a3), "r"(b0), "r"(b1));
}

// ---------------------------------------------------------------------------
// LayerNorm: one block per token, 256 threads, float4 per thread.
// ---------------------------------------------------------------------------
__global__ void ln_kernel(const float* __restrict__ x,
                          const float* __restrict__ g,
                          const float* __restrict__ b,
                          float* __restrict__ out) {
    const size_t row = blockIdx.x;
    const int t = threadIdx.x;
    float4 v = reinterpret_cast<const float4*>(x + row * FEATS)[t];

    float s  = v.x + v.y + v.z + v.w;
    float ss = v.x * v.x + v.y * v.y + v.z * v.z + v.w * v.w;

    __shared__ float smS[8], smQ[8];
    #pragma unroll
    for (int o = 16; o; o >>= 1) {
        s  += __shfl_xor_sync(0xffffffffu, s,  o);
        ss += __shfl_xor_sync(0xffffffffu, ss, o);
    }
    if ((t & 31) == 0) { smS[t >> 5] = s; smQ[t >> 5] = ss; }
    __syncthreads();
    float tS = 0.f, tQ = 0.f;
    #pragma unroll
    for (int i = 0; i < 8; i++) { tS += smS[i]; tQ += smQ[i]; }

    const float mean = tS * (1.0f / FEATS);
    const float var  = tQ * (1.0f / FEATS) - mean * mean;
    const float rstd = rsqrtf(var + LN_EPS);

    float4 gg = reinterpret_cast<const float4*>(g)[t];
    float4 bb = reinterpret_cast<const float4*>(b)[t];
    float4 o4;
    o4.x = (v.x - mean) * rstd * gg.x + bb.x;
    o4.y = (v.y - mean) * rstd * gg.y + bb.y;
    o4.z = (v.z - mean) * rstd * gg.z + bb.z;
    o4.w = (v.w - mean) * rstd * gg.w + bb.w;
    reinterpret_cast<float4*>(out + row * FEATS)[t] = o4;
}

// ---------------------------------------------------------------------------
// Double-buffered TF32 NT GEMM: C[m,n] = sum_k A[m,k] * B[n,k] (+bias,+epi)
// BM=BN=128, BK=32, 8 warps (warp tile 64x32), dynamic smem 2*(128*36)*2*4B.
// EPI: 0=none, 1=relu, 2=+res, 3=relu then +res.
// ---------------------------------------------------------------------------
template<int EPI>
__global__ void __launch_bounds__(256)
mma_gemm(const float* __restrict__ A, const float* __restrict__ B,
         float* __restrict__ C, const float* __restrict__ bias,
         const float* __restrict__ res,
         int K, int lda, int ldb, int ldc) {
    constexpr int AS_LD = BK + 4;           // 36
    constexpr int STAGE = 128 * AS_LD * 2;  // floats per stage (A+B)
    extern __shared__ float gsm[];

    const int m0 = blockIdx.y * 128;
    const int n0 = blockIdx.x * 128;

    const int tid  = threadIdx.x;
    const int wid  = tid >> 5;
    const int lane = tid & 31;
    const int lq   = lane >> 2;
    const int lr   = lane & 3;
    const int wm   = wid >> 2;          // 0..1
    const int wn   = wid & 3;           // 0..3

    float acc[4][4][4];
    #pragma unroll
    for (int i = 0; i < 4; i++)
        #pragma unroll
        for (int j = 0; j < 4; j++)
            #pragma unroll
            for (int r = 0; r < 4; r++) acc[i][j][r] = 0.f;

    const int ldr = tid >> 3;           // row 0..31 step handled by +32
    const int ldc4 = (tid & 7) << 2;    // k col

    float4 ra[4], rb[4];
    // prologue: load k0=0
    #pragma unroll
    for (int i = 0; i < 4; i++) {
        ra[i] = *reinterpret_cast<const float4*>(
            &A[(size_t)(m0 + ldr + i * 32) * lda + ldc4]);
        rb[i] = *reinterpret_cast<const float4*>(
            &B[(size_t)(n0 + ldr + i * 32) * ldb + ldc4]);
    }
    {
        float* As = gsm;
        float* Bs = gsm + 128 * AS_LD;
        #pragma unroll
        for (int i = 0; i < 4; i++) {
            float4 v = ra[i];
            v.x = f2tf32(v.x); v.y = f2tf32(v.y);
            v.z = f2tf32(v.z); v.w = f2tf32(v.w);
            *reinterpret_cast<float4*>(&As[(ldr + i * 32) * AS_LD + ldc4]) = v;
            float4 w = rb[i];
            w.x = f2tf32(w.x); w.y = f2tf32(w.y);
            w.z = f2tf32(w.z); w.w = f2tf32(w.w);
            *reinterpret_cast<float4*>(&Bs[(ldr + i * 32) * AS_LD + ldc4]) = w;
        }
    }
    __syncthreads();

    int cur = 0;
    for (int k0 = 0; k0 < K; k0 += BK) {
        const bool more = (k0 + BK) < K;
        if (more) {
            #pragma unroll
            for (int i = 0; i < 4; i++) {
                ra[i] = *reinterpret_cast<const float4*>(
                    &A[(size_t)(m0 + ldr + i * 32) * lda + k0 + BK + ldc4]);
                rb[i] = *reinterpret_cast<const float4*>(
                    &B[(size_t)(n0 + ldr + i * 32) * ldb + k0 + BK + ldc4]);
            }
        }
        // ---- compute current stage ----
        {
            const float* As = gsm + cur * STAGE;
            const float* Bs = As + 128 * AS_LD;
            #pragma unroll
            for (int kk = 0; kk < 4; kk++) {
                const int kb = kk * 8;
                uint32_t af[4][4];
                #pragma unroll
                for (int mi = 0; mi < 4; mi++) {
                    const int m = wm * 64 + mi * 16 + lq;
                    af[mi][0] = __float_as_uint(As[(m    ) * AS_LD + kb + lr    ]);
                    af[mi][1] = __float_as_uint(As[(m + 8) * AS_LD + kb + lr    ]);
                    af[mi][2] = __float_as_uint(As[(m    ) * AS_LD + kb + lr + 4]);
                    af[mi][3] = __float_as_uint(As[(m + 8) * AS_LD + kb + lr + 4]);
                }
                uint32_t bf[4][2];
                #pragma unroll
                for (int ni = 0; ni < 4; ni++) {
                    const int n = wn * 32 + ni * 8 + lq;
                    bf[ni][0] = __float_as_uint(Bs[n * AS_LD + kb + lr    ]);
                    bf[ni][1] = __float_as_uint(Bs[n * AS_LD + kb + lr + 4]);
                }
                #pragma unroll
                for (int mi = 0; mi < 4; mi++)
                    #pragma unroll
                    for (int ni = 0; ni < 4; ni++)
                        mma_tf32(acc[mi][ni], af[mi][0], af[mi][1], af[mi][2],
                                 af[mi][3], bf[ni][0], bf[ni][1]);
            }
        }
        if (more) {
            float* As = gsm + (cur ^ 1) * STAGE;
            float* Bs = As + 128 * AS_LD;
            #pragma unroll
            for (int i = 0; i < 4; i++) {
                float4 v = ra[i];
                v.x = f2tf32(v.x); v.y = f2tf32(v.y);
                v.z = f2tf32(v.z); v.w = f2tf32(v.w);
                *reinterpret_cast<float4*>(&As[(ldr + i * 32) * AS_LD + ldc4]) = v;
                float4 w = rb[i];
                w.x = f2tf32(w.x); w.y = f2tf32(w.y);
                w.z = f2tf32(w.z); w.w = f2tf32(w.w);
                *reinterpret_cast<float4*>(&Bs[(ldr + i * 32) * AS_LD + ldc4]) = w;
            }
            __syncthreads();
            cur ^= 1;
        }
    }

    // ---- epilogue ----
    #pragma unroll
    for (int mi = 0; mi < 4; mi++) {
        #pragma unroll
        for (int ni = 0; ni < 4; ni++) {
            const int r = m0 + wm * 64 + mi * 16 + lq;
            const int c = n0 + wn * 32 + ni * 8 + lr * 2;
            float2 v0, v1;
            v0.x = acc[mi][ni][0]; v0.y = acc[mi][ni][1];
            v1.x = acc[mi][ni][2]; v1.y = acc[mi][ni][3];
            float2 b2 = *reinterpret_cast<const float2*>(&bias[c]);
            v0.x += b2.x; v0.y += b2.y;
            v1.x += b2.x; v1.y += b2.y;
            if (EPI == 1 || EPI == 3) {
                v0.x = fmaxf(v0.x, 0.f); v0.y = fmaxf(v0.y, 0.f);
                v1.x = fmaxf(v1.x, 0.f); v1.y = fmaxf(v1.y, 0.f);
            }
            if (EPI == 2 || EPI == 3) {
                float2 r0 = *reinterpret_cast<const float2*>(
                    &res[(size_t)r * ldc + c]);
                float2 r1 = *reinterpret_cast<const float2*>(
                    &res[(size_t)(r + 8) * ldc + c]);
                v0.x += r0.x; v0.y += r0.y;
                v1.x += r1.x; v1.y += r1.y;
            }
            *reinterpret_cast<float2*>(&C[(size_t)r * ldc + c])       = v0;
            *reinterpret_cast<float2*>(&C[(size_t)(r + 8) * ldc + c]) = v1;
        }
    }
}

// ---------------------------------------------------------------------------
// Flash attention. One CTA per (128-row Q tile, head). 8 warps; each warp owns
// 16 Q rows. Online softmax; P re-fragmented through warp-private smem.
// Smem: sQ[128][68], sK[128][68], sV[128][72], sP[8][16][132]  = 174080 B.
// ---------------------------------------------------------------------------
__global__ void __launch_bounds__(256)
flash_kernel(const float* __restrict__ Q, const float* __restrict__ K,
             const float* __restrict__ V, float* __restrict__ Out) {
    extern __shared__ float fsm[];
    float* sQ = fsm;                 // [128][68]
    float* sK = sQ + 128 * 68;       // [128][68]  row = kv token
    float* sV = sK + 128 * 68;       // [128][72]  row = kv token (k of PV)
    float* sP = sV + 128 * 72;       // [8][16][132]

    const int bh = blockIdx.y;
    const int bb = bh >> 4;
    const int hh = bh & 15;
    const int q0 = blockIdx.x * 128;
    const size_t base = (size_t)bb * SEQ * FEATS + (size_t)hh * HD;

    const int tid  = threadIdx.x;
    const int wid  = tid >> 5;
    const int lane = tid & 31;
    const int lq   = lane >> 2;
    const int lr   = lane & 3;
    const int mrow = wid * 16 + lq;   // CTA-local Q row of this thread

    // ---- load Q tile (scaled by 1/sqrt(FEATS)=1/32, tf32) ----
    #pragma unroll
    for (int i = 0; i < 8; i++) {
        int id = tid + i * 256;
        int r = id >> 4, c = (id & 15) << 2;
        float4 v = *reinterpret_cast<const float4*>(
            &Q[base + (size_t)(q0 + r) * FEATS + c]);
        v.x = f2tf32(v.x * 0.03125f); v.y = f2tf32(v.y * 0.03125f);
        v.z = f2tf32(v.z * 0.03125f); v.w = f2tf32(v.w * 0.03125f);
        *reinterpret_cast<float4*>(&sQ[r * 68 + c]) = v;
    }

    float oacc[8][4];
    #pragma unroll
    for (int i = 0; i < 8; i++)
        #pragma unroll
        for (int r = 0; r < 4; r++) oacc[i][r] = 0.f;
    float m0 = -1e30f, m1 = -1e30f, l0 = 0.f, l1 = 0.f;
    float* sPw = sP + wid * (16 * 132);

    for (int kv0 = 0; kv0 < SEQ; kv0 += 128) {
        __syncthreads();   // prev-tile K/V consumers done (covers Q load too)
        #pragma unroll
        for (int i = 0; i < 8; i++) {
            int id = tid + i * 256;
            int r = id >> 4, c = (id & 15) << 2;
            float4 kv = *reinterpret_cast<const float4*>(
                &K[base + (size_t)(kv0 + r) * FEATS + c]);
            kv.x = f2tf32(kv.x); kv.y = f2tf32(kv.y);
            kv.z = f2tf32(kv.z); kv.w = f2tf32(kv.w);
            *reinterpret_cast<float4*>(&sK[r * 68 + c]) = kv;
            float4 vv = *reinterpret_cast<const float4*>(
                &V[base + (size_t)(kv0 + r) * FEATS + c]);
            vv.x = f2tf32(vv.x); vv.y = f2tf32(vv.y);
            vv.z = f2tf32(vv.z); vv.w = f2tf32(vv.w);
            *reinterpret_cast<float4*>(&sV[r * 72 + c]) = vv;
        }
        __syncthreads();

        // ---- S = Q K^T (per warp 16 x 128) ----
        float sacc[16][4];
        #pragma unroll
        for (int i = 0; i < 16; i++)
            #pragma unroll
            for (int r = 0; r < 4; r++) sacc[i][r] = 0.f;

        #pragma unroll
        for (int kk = 0; kk < 8; kk++) {
            const int kb = kk * 8;
            uint32_t a0 = __float_as_uint(sQ[(mrow    ) * 68 + kb + lr    ]);
            uint32_t a1 = __float_as_uint(sQ[(mrow + 8) * 68 + kb + lr    ]);
            uint32_t a2 = __float_as_uint(sQ[(mrow    ) * 68 + kb + lr + 4]);
            uint32_t a3 = __float_as_uint(sQ[(mrow + 8) * 68 + kb + lr + 4]);
            #pragma unroll
            for (int ni = 0; ni < 16; ni++) {
                const int n = ni * 8 + lq;
                uint32_t b0 = __float_as_uint(sK[n * 68 + kb + lr    ]);
                uint32_t b1 = __float_as_uint(sK[n * 68 + kb + lr + 4]);
                mma_tf32(sacc[ni], a0, a1, a2, a3, b0, b1);
            }
        }

        // ---- online softmax ----
        float mt0 = -1e30f, mt1 = -1e30f;
        #pragma unroll
        for (int ni = 0; ni < 16; ni++) {
            mt0 = fmaxf(mt0, fmaxf(sacc[ni][0], sacc[ni][1]));
            mt1 = fmaxf(mt1, fmaxf(sacc[ni][2], sacc[ni][3]));
        }
        mt0 = fmaxf(mt0, __shfl_xor_sync(0xffffffffu, mt0, 1));
        mt0 = fmaxf(mt0, __shfl_xor_sync(0xffffffffu, mt0, 2));
        mt1 = fmaxf(mt1, __shfl_xor_sync(0xffffffffu, mt1, 1));
        mt1 = fmaxf(mt1, __shfl_xor_sync(0xffffffffu, mt1, 2));

        const float mn0 = fmaxf(m0, mt0), mn1 = fmaxf(m1, mt1);
        const float al0 = __expf(m0 - mn0), al1 = __expf(m1 - mn1);
        float s0 = 0.f, s1 = 0.f;
        #pragma unroll
        for (int ni = 0; ni < 16; ni++) {
            float p00 = __expf(sacc[ni][0] - mn0);
            float p01 = __expf(sacc[ni][1] - mn0);
            float p10 = __expf(sacc[ni][2] - mn1);
            float p11 = __expf(sacc[ni][3] - mn1);
            s0 += p00 + p01; s1 += p10 + p11;
            *reinterpret_cast<float2*>(&sPw[(lq    ) * 132 + ni * 8 + lr * 2]) =
                make_float2(p00, p01);
            *reinterpret_cast<float2*>(&sPw[(lq + 8) * 132 + ni * 8 + lr * 2]) =
                make_float2(p10, p11);
        }
        s0 += __shfl_xor_sync(0xffffffffu, s0, 1);
        s0 += __shfl_xor_sync(0xffffffffu, s0, 2);
        s1 += __shfl_xor_sync(0xffffffffu, s1, 1);
        s1 += __shfl_xor_sync(0xffffffffu, s1, 2);
        l0 = l0 * al0 + s0; l1 = l1 * al1 + s1;
        m0 = mn0; m1 = mn1;
        #pragma unroll
        for (int oni = 0; oni < 8; oni++) {
            oacc[oni][0] *= al0; oacc[oni][1] *= al0;
            oacc[oni][2] *= al1; oacc[oni][3] *= al1;
        }
        __syncwarp();

        // ---- O += P V  (per warp 16 x 64, K=128) ----
        #pragma unroll
        for (int kk = 0; kk < 16; kk++) {
            const int kb = kk * 8;
            uint32_t a0 = __float_as_uint(sPw[(lq    ) * 132 + kb + lr    ]);
            uint32_t a1 = __float_as_uint(sPw[(lq + 8) * 132 + kb + lr    ]);
            uint32_t a2 = __float_as_uint(sPw[(lq    ) * 132 + kb + lr + 4]);
            uint32_t a3 = __float_as_uint(sPw[(lq + 8) * 132 + kb + lr + 4]);
            #pragma unroll
            for (int oni = 0; oni < 8; oni++) {
                const int n = oni * 8 + lq;
                uint32_t b0 = __float_as_uint(sV[(kb + lr    ) * 72 + n]);
                uint32_t b1 = __float_as_uint(sV[(kb + lr + 4) * 72 + n]);
                mma_tf32(oacc[oni], a0, a1, a2, a3, b0, b1);
            }
        }
        __syncwarp();   // sPw reads done before next tile's overwrites
    }

    // ---- epilogue: normalize and write ----
    const float inv0 = __fdividef(1.f, l0);
    const float inv1 = __fdividef(1.f, l1);
    const size_t r0 = base + (size_t)(q0 + mrow) * FEATS;
    const size_t r1 = r0 + (size_t)8 * FEATS;
    #pragma unroll
    for (int oni = 0; oni < 8; oni++) {
        const int c = oni * 8 + lr * 2;
        *reinterpret_cast<float2*>(&Out[r0 + c]) =
            make_float2(oacc[oni][0] * inv0, oacc[oni][1] * inv0);
        *reinterpret_cast<float2*>(&Out[r1 + c]) =
            make_float2(oacc[oni][2] * inv1, oacc[oni][3] * inv1);
    }
}

// ---------------------------------------------------------------------------
#define GEMM_SMEM (2 * 128 * (BK + 4) * 2 * 4)     // 73728 B
#define FLASH_SMEM ((128*68 + 128*68 + 128*72 + 8*16*132) * 4)  // 174080 B

extern "C" void kernel_launch(void* const* d_in, const int* in_sizes, int n_in,
                              void* d_out, int out_size) {
    (void)in_sizes; (void)n_in; (void)out_size;
    const float* x    = (const float*)d_in[0];
    const float* ln1g = (const float*)d_in[1];
    const float* ln1b = (const float*)d_in[2];
    const float* wq   = (const float*)d_in[3];
    const float* bq   = (const float*)d_in[4];
    const float* wk   = (const float*)d_in[5];
    const float* bk   = (const float*)d_in[6];
    const float* wv   = (const float*)d_in[7];
    const float* bv   = (const float*)d_in[8];
    const float* wo   = (const float*)d_in[9];
    const float* bo   = (const float*)d_in[10];
    const float* ln2g = (const float*)d_in[11];
    const float* ln2b = (const float*)d_in[12];
    const float* w1   = (const float*)d_in[13];
    const float* b1   = (const float*)d_in[14];
    const float* w2   = (const float*)d_in[15];
    const float* b2   = (const float*)d_in[16];
    float* out = (float*)d_out;

    float *h1, *q, *k, *v, *attn, *out1, *h2, *m1;
    cudaGetSymbolAddress((void**)&h1,   g_h1);
    cudaGetSymbolAddress((void**)&q,    g_q);
    cudaGetSymbolAddress((void**)&k,    g_k);
    cudaGetSymbolAddress((void**)&v,    g_v);
    cudaGetSymbolAddress((void**)&attn, g_attn);
    cudaGetSymbolAddress((void**)&out1, g_out1);
    cudaGetSymbolAddress((void**)&h2,   g_h2);
    cudaGetSymbolAddress((void**)&m1,   g_m1);

    cudaFuncSetAttribute(mma_gemm<0>, cudaFuncAttributeMaxDynamicSharedMemorySize, GEMM_SMEM);
    cudaFuncSetAttribute(mma_gemm<1>, cudaFuncAttributeMaxDynamicSharedMemorySize, GEMM_SMEM);
    cudaFuncSetAttribute(mma_gemm<2>, cudaFuncAttributeMaxDynamicSharedMemorySize, GEMM_SMEM);
    cudaFuncSetAttribute(mma_gemm<3>, cudaFuncAttributeMaxDynamicSharedMemorySize, GEMM_SMEM);
    cudaFuncSetAttribute(flash_kernel, cudaFuncAttributeMaxDynamicSharedMemorySize, FLASH_SMEM);

    // 1) LN1
    ln_kernel<<<TOK, 256>>>(x, ln1g, ln1b, h1);

    // 2) Q/K/V projections
    {
        dim3 grid(FEATS / 128, TOK / 128);
        mma_gemm<0><<<grid, 256, GEMM_SMEM>>>(h1, wq, q, bq, nullptr,
                                              FEATS, FEATS, FEATS, FEATS);
        mma_gemm<0><<<grid, 256, GEMM_SMEM>>>(h1, wk, k, bk, nullptr,
                                              FEATS, FEATS, FEATS, FEATS);
        mma_gemm<0><<<grid, 256, GEMM_SMEM>>>(h1, wv, v, bv, nullptr,
                                              FEATS, FEATS, FEATS, FEATS);
    }

    // 3) fused attention
    {
        dim3 grid(SEQ / 128, BATCH * HEADS);
        flash_kernel<<<grid, 256, FLASH_SMEM>>>(q, k, v, attn);
    }

    // 4) O projection + residual
    {
        dim3 grid(FEATS / 128, TOK / 128);
        mma_gemm<2><<<grid, 256, GEMM_SMEM>>>(attn, wo, out1, bo, x,
                                              FEATS, FEATS, FEATS, FEATS);
    }

    // 5) LN2
    ln_kernel<<<TOK, 256>>>(out1, ln2g, ln2b, h2);

    // 6) MLP up: relu(h2 @ w1^T + b1)
    {
        dim3 grid(HIDDEN / 128, TOK / 128);
        mma_gemm<1><<<grid, 256, GEMM_SMEM>>>(h2, w1, m1, b1, nullptr,
                                              FEATS, FEATS, FEATS, HIDDEN);
    }

    // 7) MLP down: relu(m1 @ w2^T + b2) + out1
    {
        dim3 grid(FEATS / 128, TOK / 128);
        mma_gemm<3><<<grid, 256, GEMM_SMEM>>>(m1, w2, out, b2, out1,
                                              HIDDEN, HIDDEN, HIDDEN, FEATS);
    }
}

// round 4
// speedup vs baseline: 3.4227x; 1.2093x over previous
#include <cuda_runtime.h>
#include <cstdint>
#include <cstddef>

#define FEATS  1024
#define SEQ    2048
#define BATCH  2
#define TOK    (BATCH * SEQ)     // 4096
#define HEADS  16
#define HD     64
#define HIDDEN 4096
#define LN_EPS 1e-5f
#define BK     32

// ---- scratch ----
__device__ float g_h1[(size_t)TOK * FEATS];
__device__ float g_q [(size_t)TOK * FEATS];
__device__ float g_k [(size_t)TOK * FEATS];
__device__ float g_v [(size_t)TOK * FEATS];
__device__ float g_attn[(size_t)TOK * FEATS];
__device__ float g_out1[(size_t)TOK * FEATS];
__device__ float g_h2 [(size_t)TOK * FEATS];
__device__ float g_m1 [(size_t)TOK * HIDDEN];

// ---------------------------------------------------------------------------
__device__ __forceinline__ void mma_tf32(float c[4],
                                         uint32_t a0, uint32_t a1,
                                         uint32_t a2, uint32_t a3,
                                         uint32_t b0, uint32_t b1) {
    asm volatile(
        "mma.sync.aligned.m16n8k8.row.col.f32.tf32.tf32.f32 "
        "{%0,%1,%2,%3}, {%4,%5,%6,%7}, {%8,%9}, {%0,%1,%2,%3};\n"
        : "+f"(c[0]), "+f"(c[1]), "+f"(c[2]), "+f"(c[3])
        : "r"(a0), "r"(a1), "r"(a2), "r"(a3), "r"(b0), "r"(b1));
}

__device__ __forceinline__ void ldsm_x4(uint32_t r[4], uint32_t addr) {
    asm volatile("ldmatrix.sync.aligned.m8n8.x4.shared.b16 {%0,%1,%2,%3}, [%4];"
                 : "=r"(r[0]), "=r"(r[1]), "=r"(r[2]), "=r"(r[3]) : "r"(addr));
}

#define CP_ASYNC16(dst, src) \
    asm volatile("cp.async.cg.shared.global [%0], [%1], 16;\n" \
                 :: "r"(dst), "l"(src))
#define CP_COMMIT() asm volatile("cp.async.commit_group;\n")
#define CP_WAIT(N)  asm volatile("cp.async.wait_group %0;\n" :: "n"(N))

__device__ __forceinline__ uint32_t smem_u32(const void* p) {
    return (uint32_t)__cvta_generic_to_shared(p);
}

// ---------------------------------------------------------------------------
// LayerNorm
// ---------------------------------------------------------------------------
__global__ void ln_kernel(const float* __restrict__ x,
                          const float* __restrict__ g,
                          const float* __restrict__ b,
                          float* __restrict__ out) {
    const size_t row = blockIdx.x;
    const int t = threadIdx.x;
    float4 v = reinterpret_cast<const float4*>(x + row * FEATS)[t];

    float s  = v.x + v.y + v.z + v.w;
    float ss = v.x * v.x + v.y * v.y + v.z * v.z + v.w * v.w;

    __shared__ float smS[8], smQ[8];
    #pragma unroll
    for (int o = 16; o; o >>= 1) {
        s  += __shfl_xor_sync(0xffffffffu, s,  o);
        ss += __shfl_xor_sync(0xffffffffu, ss, o);
    }
    if ((t & 31) == 0) { smS[t >> 5] = s; smQ[t >> 5] = ss; }
    __syncthreads();
    float tS = 0.f, tQ = 0.f;
    #pragma unroll
    for (int i = 0; i < 8; i++) { tS += smS[i]; tQ += smQ[i]; }

    const float mean = tS * (1.0f / FEATS);
    const float var  = tQ * (1.0f / FEATS) - mean * mean;
    const float rstd = rsqrtf(var + LN_EPS);

    float4 gg = reinterpret_cast<const float4*>(g)[t];
    float4 bb = reinterpret_cast<const float4*>(b)[t];
    float4 o4;
    o4.x = (v.x - mean) * rstd * gg.x + bb.x;
    o4.y = (v.y - mean) * rstd * gg.y + bb.y;
    o4.z = (v.z - mean) * rstd * gg.z + bb.z;
    o4.w = (v.w - mean) * rstd * gg.w + bb.w;
    reinterpret_cast<float4*>(out + row * FEATS)[t] = o4;
}

// ---------------------------------------------------------------------------
// TF32 NT GEMM, 2-stage cp.async pipeline + ldmatrix fragments.
// BM=BN=128, BK=32, 8 warps (64x32 warp tile). TF32 via MMA truncation.
// SPLIT: blockIdx.x selects one of 3 (B, bias, C) triples (QKV fusion).
// EPI: 0=none, 1=relu, 2=+res, 3=relu+res.
// ---------------------------------------------------------------------------
template<int EPI, bool SPLIT>
__global__ void __launch_bounds__(256)
mma_gemm(const float* __restrict__ A,
         const float* __restrict__ B0, const float* __restrict__ B1,
         const float* __restrict__ B2,
         float* __restrict__ C0, float* __restrict__ C1,
         float* __restrict__ C2,
         const float* __restrict__ bias0, const float* __restrict__ bias1,
         const float* __restrict__ bias2,
         const float* __restrict__ res,
         int K, int lda, int ldb, int ldc) {
    constexpr int AS_LD   = BK + 4;                  // 36 floats
    constexpr int STAGE_B = 2 * 128 * AS_LD * 4;     // bytes per stage (A+B)
    constexpr int BOFF_B  = 128 * AS_LD * 4;         // B offset within stage
    extern __shared__ float gsm[];
    const uint32_t smem = smem_u32(gsm);

    const float* B; float* C; const float* bias; int n0;
    if (SPLIT) {
        const int w = blockIdx.x >> 3;
        n0   = (blockIdx.x & 7) * 128;
        B    = (w == 0) ? B0 : (w == 1) ? B1 : B2;
        C    = (w == 0) ? C0 : (w == 1) ? C1 : C2;
        bias = (w == 0) ? bias0 : (w == 1) ? bias1 : bias2;
    } else {
        B = B0; C = C0; bias = bias0;
        n0 = blockIdx.x * 128;
    }
    const int m0 = blockIdx.y * 128;

    const int tid  = threadIdx.x;
    const int wid  = tid >> 5;
    const int lane = tid & 31;
    const int wm   = wid >> 2;
    const int wn   = wid & 3;

    // cp.async mapping: row = tid>>3 (+32*i), col = (tid&7)*4
    const int cr = tid >> 3;
    const int cc = (tid & 7) << 2;
    const uint32_t dstA0 = smem + (uint32_t)((cr * AS_LD + cc) * 4);
    const uint32_t dstB0 = dstA0 + BOFF_B;
    const float* srcA = A + (size_t)(m0 + cr) * lda + cc;
    const float* srcB = B + (size_t)(n0 + cr) * ldb + cc;

    // ldmatrix per-thread offsets (bytes, relative to stage A/B base)
    const int ar = (lane & 7) + ((lane >> 3) & 1) * 8;
    const int ac = (lane >> 4) * 4;
    const int br = ((lane >> 4) & 1) * 8 + (lane & 7);
    const int bc = ((lane >> 3) & 1) * 4;
    uint32_t aOff[4], bOff[2];
    #pragma unroll
    for (int mi = 0; mi < 4; mi++)
        aOff[mi] = (uint32_t)(((wm * 64 + mi * 16 + ar) * AS_LD + ac) * 4);
    #pragma unroll
    for (int pi = 0; pi < 2; pi++)
        bOff[pi] = (uint32_t)(((wn * 32 + pi * 16 + br) * AS_LD + bc) * 4)
                   + BOFF_B;

    float acc[4][4][4];
    #pragma unroll
    for (int i = 0; i < 4; i++)
        #pragma unroll
        for (int j = 0; j < 4; j++)
            #pragma unroll
            for (int r = 0; r < 4; r++) acc[i][j][r] = 0.f;

    // ---- prologue: stage 0 and stage 1 ----
    #pragma unroll
    for (int i = 0; i < 4; i++) {
        CP_ASYNC16(dstA0 + i * 32 * AS_LD * 4, srcA + (size_t)i * 32 * lda);
        CP_ASYNC16(dstB0 + i * 32 * AS_LD * 4, srcB + (size_t)i * 32 * ldb);
    }
    CP_COMMIT();
    if (K > BK) {
        #pragma unroll
        for (int i = 0; i < 4; i++) {
            CP_ASYNC16(dstA0 + STAGE_B + i * 32 * AS_LD * 4,
                       srcA + (size_t)i * 32 * lda + BK);
            CP_ASYNC16(dstB0 + STAGE_B + i * 32 * AS_LD * 4,
                       srcB + (size_t)i * 32 * ldb + BK);
        }
    }
    CP_COMMIT();
    CP_WAIT(1);
    __syncthreads();

    int cur = 0;
    for (int k0 = 0; k0 < K; k0 += BK) {
        const uint32_t stA = smem + cur * STAGE_B;
        #pragma unroll
        for (int kk = 0; kk < 4; kk++) {
            const uint32_t kbB = kk * 32;   // 8 floats
            uint32_t af[4][4], bfr[2][4];
            #pragma unroll
            for (int mi = 0; mi < 4; mi++) ldsm_x4(af[mi], stA + aOff[mi] + kbB);
            #pragma unroll
            for (int pi = 0; pi < 2; pi++) ldsm_x4(bfr[pi], stA + bOff[pi] + kbB);
            #pragma unroll
            for (int mi = 0; mi < 4; mi++)
                #pragma unroll
                for (int ni = 0; ni < 4; ni++)
                    mma_tf32(acc[mi][ni], af[mi][0], af[mi][1], af[mi][2],
                             af[mi][3], bfr[ni >> 1][(ni & 1) * 2],
                             bfr[ni >> 1][(ni & 1) * 2 + 1]);
        }
        __syncthreads();                         // all warps done reading cur
        if (k0 + 2 * BK < K) {
            const uint32_t d = smem + cur * STAGE_B;
            const int kn = k0 + 2 * BK;
            #pragma unroll
            for (int i = 0; i < 4; i++) {
                CP_ASYNC16(dstA0 - smem + d + i * 32 * AS_LD * 4,
                           srcA + (size_t)i * 32 * lda + kn);
                CP_ASYNC16(dstB0 - smem + d + i * 32 * AS_LD * 4,
                           srcB + (size_t)i * 32 * ldb + kn);
            }
        }
        CP_COMMIT();
        CP_WAIT(1);                              // other stage complete
        __syncthreads();
        cur ^= 1;
    }

    // ---- epilogue ----
    const int lq = lane >> 2, lr = lane & 3;
    #pragma unroll
    for (int mi = 0; mi < 4; mi++) {
        #pragma unroll
        for (int ni = 0; ni < 4; ni++) {
            const int r = m0 + wm * 64 + mi * 16 + lq;
            const int c = n0 + wn * 32 + ni * 8 + lr * 2;
            float2 v0, v1;
            v0.x = acc[mi][ni][0]; v0.y = acc[mi][ni][1];
            v1.x = acc[mi][ni][2]; v1.y = acc[mi][ni][3];
            float2 b2 = *reinterpret_cast<const float2*>(&bias[c]);
            v0.x += b2.x; v0.y += b2.y;
            v1.x += b2.x; v1.y += b2.y;
            if (EPI == 1 || EPI == 3) {
                v0.x = fmaxf(v0.x, 0.f); v0.y = fmaxf(v0.y, 0.f);
                v1.x = fmaxf(v1.x, 0.f); v1.y = fmaxf(v1.y, 0.f);
            }
            if (EPI == 2 || EPI == 3) {
                float2 r0 = *reinterpret_cast<const float2*>(
                    &res[(size_t)r * ldc + c]);
                float2 r1 = *reinterpret_cast<const float2*>(
                    &res[(size_t)(r + 8) * ldc + c]);
                v0.x += r0.x; v0.y += r0.y;
                v1.x += r1.x; v1.y += r1.y;
            }
            *reinterpret_cast<float2*>(&C[(size_t)r * ldc + c])       = v0;
            *reinterpret_cast<float2*>(&C[(size_t)(r + 8) * ldc + c]) = v1;
        }
    }
}

// ---------------------------------------------------------------------------
// Flash attention. One CTA per (128-row Q tile, head). 8 warps, 16 Q rows
// each. K/V staged by cp.async (raw fp32; MMA truncates to tf32).
// ---------------------------------------------------------------------------
__global__ void __launch_bounds__(256)
flash_kernel(const float* __restrict__ Q, const float* __restrict__ K,
             const float* __restrict__ V, float* __restrict__ Out) {
    extern __shared__ float fsm[];
    float* sQ = fsm;                 // [128][68]
    float* sK = sQ + 128 * 68;       // [128][68]
    float* sV = sK + 128 * 68;       // [128][72]
    float* sP = sV + 128 * 72;       // [8][16][132]

    const int bh = blockIdx.y;
    const int bb = bh >> 4;
    const int hh = bh & 15;
    const int q0 = blockIdx.x * 128;
    const size_t base = (size_t)bb * SEQ * FEATS + (size_t)hh * HD;

    const int tid  = threadIdx.x;
    const int wid  = tid >> 5;
    const int lane = tid & 31;
    const int lq   = lane >> 2;
    const int lr   = lane & 3;
    const int mrow = wid * 16 + lq;

    // ---- load Q (scale by 1/32; fp32, MMA truncates) ----
    #pragma unroll
    for (int i = 0; i < 8; i++) {
        int id = tid + i * 256;
        int r = id >> 4, c = (id & 15) << 2;
        float4 v = *reinterpret_cast<const float4*>(
            &Q[base + (size_t)(q0 + r) * FEATS + c]);
        v.x *= 0.03125f; v.y *= 0.03125f; v.z *= 0.03125f; v.w *= 0.03125f;
        *reinterpret_cast<float4*>(&sQ[r * 68 + c]) = v;
    }

    // cp.async mapping for K/V: row = tid>>4, col = (tid&15)*4, 8 row-steps
    const int kr = tid >> 4;
    const int kc = (tid & 15) << 2;
    const uint32_t dK = smem_u32(&sK[kr * 68 + kc]);
    const uint32_t dV = smem_u32(&sV[kr * 72 + kc]);

    float oacc[8][4];
    #pragma unroll
    for (int i = 0; i < 8; i++)
        #pragma unroll
        for (int r = 0; r < 4; r++) oacc[i][r] = 0.f;
    float m0 = -1e30f, m1 = -1e30f, l0 = 0.f, l1 = 0.f;
    float* sPw = sP + wid * (16 * 132);

    for (int kv0 = 0; kv0 < SEQ; kv0 += 128) {
        __syncthreads();   // previous-tile K/V readers done (covers Q store)
        {
            const float* srcK = &K[base + (size_t)(kv0 + kr) * FEATS + kc];
            const float* srcV = &V[base + (size_t)(kv0 + kr) * FEATS + kc];
            #pragma unroll
            for (int i = 0; i < 8; i++) {
                CP_ASYNC16(dK + i * 16 * 68 * 4, srcK + (size_t)i * 16 * FEATS);
                CP_ASYNC16(dV + i * 16 * 72 * 4, srcV + (size_t)i * 16 * FEATS);
            }
        }
        CP_COMMIT();
        CP_WAIT(0);
        __syncthreads();

        // ---- S = Q K^T (warp: 16 x 128) ----
        float sacc[16][4];
        #pragma unroll
        for (int i = 0; i < 16; i++)
            #pragma unroll
            for (int r = 0; r < 4; r++) sacc[i][r] = 0.f;

        #pragma unroll
        for (int kk = 0; kk < 8; kk++) {
            const int kb = kk * 8;
            uint32_t a0 = __float_as_uint(sQ[(mrow    ) * 68 + kb + lr    ]);
            uint32_t a1 = __float_as_uint(sQ[(mrow + 8) * 68 + kb + lr    ]);
            uint32_t a2 = __float_as_uint(sQ[(mrow    ) * 68 + kb + lr + 4]);
            uint32_t a3 = __float_as_uint(sQ[(mrow + 8) * 68 + kb + lr + 4]);
            #pragma unroll
            for (int ni = 0; ni < 16; ni++) {
                const int n = ni * 8 + lq;
                uint32_t b0 = __float_as_uint(sK[n * 68 + kb + lr    ]);
                uint32_t b1 = __float_as_uint(sK[n * 68 + kb + lr + 4]);
                mma_tf32(sacc[ni], a0, a1, a2, a3, b0, b1);
            }
        }

        // ---- online softmax ----
        float mt0 = -1e30f, mt1 = -1e30f;
        #pragma unroll
        for (int ni = 0; ni < 16; ni++) {
            mt0 = fmaxf(mt0, fmaxf(sacc[ni][0], sacc[ni][1]));
            mt1 = fmaxf(mt1, fmaxf(sacc[ni][2], sacc[ni][3]));
        }
        mt0 = fmaxf(mt0, __shfl_xor_sync(0xffffffffu, mt0, 1));
        mt0 = fmaxf(mt0, __shfl_xor_sync(0xffffffffu, mt0, 2));
        mt1 = fmaxf(mt1, __shfl_xor_sync(0xffffffffu, mt1, 1));
        mt1 = fmaxf(mt1, __shfl_xor_sync(0xffffffffu, mt1, 2));

        const float mn0 = fmaxf(m0, mt0), mn1 = fmaxf(m1, mt1);
        const float al0 = __expf(m0 - mn0), al1 = __expf(m1 - mn1);
        float s0 = 0.f, s1 = 0.f;
        #pragma unroll
        for (int ni = 0; ni < 16; ni++) {
            float p00 = __expf(sacc[ni][0] - mn0);
            float p01 = __expf(sacc[ni][1] - mn0);
            float p10 = __expf(sacc[ni][2] - mn1);
            float p11 = __expf(sacc[ni][3] - mn1);
            s0 += p00 + p01; s1 += p10 + p11;
            *reinterpret_cast<float2*>(&sPw[(lq    ) * 132 + ni * 8 + lr * 2]) =
                make_float2(p00, p01);
            *reinterpret_cast<float2*>(&sPw[(lq + 8) * 132 + ni * 8 + lr * 2]) =
                make_float2(p10, p11);
        }
        s0 += __shfl_xor_sync(0xffffffffu, s0, 1);
        s0 += __shfl_xor_sync(0xffffffffu, s0, 2);
        s1 += __shfl_xor_sync(0xffffffffu, s1, 1);
        s1 += __shfl_xor_sync(0xffffffffu, s1, 2);
        l0 = l0 * al0 + s0; l1 = l1 * al1 + s1;
        m0 = mn0; m1 = mn1;
        #pragma unroll
        for (int oni = 0; oni < 8; oni++) {
            oacc[oni][0] *= al0; oacc[oni][1] *= al0;
            oacc[oni][2] *= al1; oacc[oni][3] *= al1;
        }
        __syncwarp();

        // ---- O += P V ----
        #pragma unroll
        for (int kk = 0; kk < 16; kk++) {
            const int kb = kk * 8;
            uint32_t a0 = __float_as_uint(sPw[(lq    ) * 132 + kb + lr    ]);
            uint32_t a1 = __float_as_uint(sPw[(lq + 8) * 132 + kb + lr    ]);
            uint32_t a2 = __float_as_uint(sPw[(lq    ) * 132 + kb + lr + 4]);
            uint32_t a3 = __float_as_uint(sPw[(lq + 8) * 132 + kb + lr + 4]);
            #pragma unroll
            for (int oni = 0; oni < 8; oni++) {
                const int n = oni * 8 + lq;
                uint32_t b0 = __float_as_uint(sV[(kb + lr    ) * 72 + n]);
                uint32_t b1 = __float_as_uint(sV[(kb + lr + 4) * 72 + n]);
                mma_tf32(oacc[oni], a0, a1, a2, a3, b0, b1);
            }
        }
        __syncwarp();
    }

    // ---- epilogue ----
    const float inv0 = __fdividef(1.f, l0);
    const float inv1 = __fdividef(1.f, l1);
    const size_t r0 = base + (size_t)(q0 + mrow) * FEATS;
    const size_t r1 = r0 + (size_t)8 * FEATS;
    #pragma unroll
    for (int oni = 0; oni < 8; oni++) {
        const int c = oni * 8 + lr * 2;
        *reinterpret_cast<float2*>(&Out[r0 + c]) =
            make_float2(oacc[oni][0] * inv0, oacc[oni][1] * inv0);
        *reinterpret_cast<float2*>(&Out[r1 + c]) =
            make_float2(oacc[oni][2] * inv1, oacc[oni][3] * inv1);
    }
}

// ---------------------------------------------------------------------------
#define GEMM_SMEM  (2 * 2 * 128 * (BK + 4) * 4)                  // 73728 B
#define FLASH_SMEM ((128*68 + 128*68 + 128*72 + 8*16*132) * 4)   // 174080 B

extern "C" void kernel_launch(void* const* d_in, const int* in_sizes, int n_in,
                              void* d_out, int out_size) {
    (void)in_sizes; (void)n_in; (void)out_size;
    const float* x    = (const float*)d_in[0];
    const float* ln1g = (const float*)d_in[1];
    const float* ln1b = (const float*)d_in[2];
    const float* wq   = (const float*)d_in[3];
    const float* bq   = (const float*)d_in[4];
    const float* wk   = (const float*)d_in[5];
    const float* bk   = (const float*)d_in[6];
    const float* wv   = (const float*)d_in[7];
    const float* bv   = (const float*)d_in[8];
    const float* wo   = (const float*)d_in[9];
    const float* bo   = (const float*)d_in[10];
    const float* ln2g = (const float*)d_in[11];
    const float* ln2b = (const float*)d_in[12];
    const float* w1   = (const float*)d_in[13];
    const float* b1   = (const float*)d_in[14];
    const float* w2   = (const float*)d_in[15];
    const float* b2   = (const float*)d_in[16];
    float* out = (float*)d_out;

    float *h1, *q, *k, *v, *attn, *out1, *h2, *m1;
    cudaGetSymbolAddress((void**)&h1,   g_h1);
    cudaGetSymbolAddress((void**)&q,    g_q);
    cudaGetSymbolAddress((void**)&k,    g_k);
    cudaGetSymbolAddress((void**)&v,    g_v);
    cudaGetSymbolAddress((void**)&attn, g_attn);
    cudaGetSymbolAddress((void**)&out1, g_out1);
    cudaGetSymbolAddress((void**)&h2,   g_h2);
    cudaGetSymbolAddress((void**)&m1,   g_m1);

    cudaFuncSetAttribute(mma_gemm<0,true>,  cudaFuncAttributeMaxDynamicSharedMemorySize, GEMM_SMEM);
    cudaFuncSetAttribute(mma_gemm<1,false>, cudaFuncAttributeMaxDynamicSharedMemorySize, GEMM_SMEM);
    cudaFuncSetAttribute(mma_gemm<2,false>, cudaFuncAttributeMaxDynamicSharedMemorySize, GEMM_SMEM);
    cudaFuncSetAttribute(mma_gemm<3,false>, cudaFuncAttributeMaxDynamicSharedMemorySize, GEMM_SMEM);
    cudaFuncSetAttribute(flash_kernel, cudaFuncAttributeMaxDynamicSharedMemorySize, FLASH_SMEM);

    // 1) LN1
    ln_kernel<<<TOK, 256>>>(x, ln1g, ln1b, h1);

    // 2) fused Q/K/V projections (one launch, 768 CTAs)
    {
        dim3 grid(24, TOK / 128);
        mma_gemm<0,true><<<grid, 256, GEMM_SMEM>>>(
            h1, wq, wk, wv, q, k, v, bq, bk, bv, nullptr,
            FEATS, FEATS, FEATS, FEATS);
    }

    // 3) fused attention
    {
        dim3 grid(SEQ / 128, BATCH * HEADS);
        flash_kernel<<<grid, 256, FLASH_SMEM>>>(q, k, v, attn);
    }

    // 4) O projection + residual
    {
        dim3 grid(FEATS / 128, TOK / 128);
        mma_gemm<2,false><<<grid, 256, GEMM_SMEM>>>(
            attn, wo, nullptr, nullptr, out1, nullptr, nullptr,
            bo, nullptr, nullptr, x, FEATS, FEATS, FEATS, FEATS);
    }

    // 5) LN2
    ln_kernel<<<TOK, 256>>>(out1, ln2g, ln2b, h2);

    // 6) MLP up: relu(h2 @ w1^T + b1)
    {
        dim3 grid(HIDDEN / 128, TOK / 128);
        mma_gemm<1,false><<<grid, 256, GEMM_SMEM>>>(
            h2, w1, nullptr, nullptr, m1, nullptr, nullptr,
            b1, nullptr, nullptr, nullptr, FEATS, FEATS, FEATS, HIDDEN);
    }

    // 7) MLP down: relu(m1 @ w2^T + b2) + out1
    {
        dim3 grid(FEATS / 128, TOK / 128);
        mma_gemm<3,false><<<grid, 256, GEMM_SMEM>>>(
            m1, w2, nullptr, nullptr, out, nullptr, nullptr,
            b2, nullptr, nullptr, out1, HIDDEN, HIDDEN, HIDDEN, FEATS);
    }
}

// round 5
// speedup vs baseline: 3.7356x; 1.0914x over previous
#include <cuda_runtime.h>
#include <cstdint>
#include <cstddef>

#define FEATS  1024
#define SEQ    2048
#define BATCH  2
#define TOK    (BATCH * SEQ)     // 4096
#define HEADS  16
#define HD     64
#define HIDDEN 4096
#define LN_EPS 1e-5f
#define BK     32

// ---- scratch ----
__device__ float g_h1[(size_t)TOK * FEATS];
__device__ float g_q [(size_t)TOK * FEATS];
__device__ float g_k [(size_t)TOK * FEATS];
__device__ float g_v [(size_t)TOK * FEATS];
__device__ float g_attn[(size_t)TOK * FEATS];
__device__ float g_out1[(size_t)TOK * FEATS];
__device__ float g_h2 [(size_t)TOK * FEATS];
__device__ float g_m1 [(size_t)TOK * HIDDEN];

// ---------------------------------------------------------------------------
__device__ __forceinline__ void mma_tf32(float c[4],
                                         uint32_t a0, uint32_t a1,
                                         uint32_t a2, uint32_t a3,
                                         uint32_t b0, uint32_t b1) {
    asm volatile(
        "mma.sync.aligned.m16n8k8.row.col.f32.tf32.tf32.f32 "
        "{%0,%1,%2,%3}, {%4,%5,%6,%7}, {%8,%9}, {%0,%1,%2,%3};\n"
        : "+f"(c[0]), "+f"(c[1]), "+f"(c[2]), "+f"(c[3])
        : "r"(a0), "r"(a1), "r"(a2), "r"(a3), "r"(b0), "r"(b1));
}

__device__ __forceinline__ void ldsm_x4(uint32_t r[4], uint32_t addr) {
    asm volatile("ldmatrix.sync.aligned.m8n8.x4.shared.b16 {%0,%1,%2,%3}, [%4];"
                 : "=r"(r[0]), "=r"(r[1]), "=r"(r[2]), "=r"(r[3]) : "r"(addr));
}

#define CP_ASYNC16(dst, src) \
    asm volatile("cp.async.cg.shared.global [%0], [%1], 16;\n" \
                 :: "r"(dst), "l"(src))
#define CP_COMMIT() asm volatile("cp.async.commit_group;\n")
#define CP_WAIT(N)  asm volatile("cp.async.wait_group %0;\n" :: "n"(N))

__device__ __forceinline__ uint32_t smem_u32(const void* p) {
    return (uint32_t)__cvta_generic_to_shared(p);
}

// ---------------------------------------------------------------------------
// LayerNorm
// ---------------------------------------------------------------------------
__global__ void ln_kernel(const float* __restrict__ x,
                          const float* __restrict__ g,
                          const float* __restrict__ b,
                          float* __restrict__ out) {
    const size_t row = blockIdx.x;
    const int t = threadIdx.x;
    float4 v = reinterpret_cast<const float4*>(x + row * FEATS)[t];

    float s  = v.x + v.y + v.z + v.w;
    float ss = v.x * v.x + v.y * v.y + v.z * v.z + v.w * v.w;

    __shared__ float smS[8], smQ[8];
    #pragma unroll
    for (int o = 16; o; o >>= 1) {
        s  += __shfl_xor_sync(0xffffffffu, s,  o);
        ss += __shfl_xor_sync(0xffffffffu, ss, o);
    }
    if ((t & 31) == 0) { smS[t >> 5] = s; smQ[t >> 5] = ss; }
    __syncthreads();
    float tS = 0.f, tQ = 0.f;
    #pragma unroll
    for (int i = 0; i < 8; i++) { tS += smS[i]; tQ += smQ[i]; }

    const float mean = tS * (1.0f / FEATS);
    const float var  = tQ * (1.0f / FEATS) - mean * mean;
    const float rstd = rsqrtf(var + LN_EPS);

    float4 gg = reinterpret_cast<const float4*>(g)[t];
    float4 bb = reinterpret_cast<const float4*>(b)[t];
    float4 o4;
    o4.x = (v.x - mean) * rstd * gg.x + bb.x;
    o4.y = (v.y - mean) * rstd * gg.y + bb.y;
    o4.z = (v.z - mean) * rstd * gg.z + bb.z;
    o4.w = (v.w - mean) * rstd * gg.w + bb.w;
    reinterpret_cast<float4*>(out + row * FEATS)[t] = o4;
}

// ---------------------------------------------------------------------------
// TF32 NT GEMM, 3-stage cp.async pipeline, one __syncthreads per K-iter.
// BM=BN=128, BK=32, 8 warps (64x32 warp tile). 2 CTAs/SM.
// ---------------------------------------------------------------------------
template<int EPI, bool SPLIT>
__global__ void __launch_bounds__(256, 2)
mma_gemm(const float* __restrict__ A,
         const float* __restrict__ B0, const float* __restrict__ B1,
         const float* __restrict__ B2,
         float* __restrict__ C0, float* __restrict__ C1,
         float* __restrict__ C2,
         const float* __restrict__ bias0, const float* __restrict__ bias1,
         const float* __restrict__ bias2,
         const float* __restrict__ res,
         int K, int lda, int ldb, int ldc) {
    constexpr int AS_LD   = BK + 4;                  // 36 floats
    constexpr int STAGE_B = 2 * 128 * AS_LD * 4;     // bytes per stage (A+B)
    constexpr int BOFF_B  = 128 * AS_LD * 4;
    extern __shared__ float gsm[];
    const uint32_t smem = smem_u32(gsm);

    const float* B; float* C; const float* bias; int n0;
    if (SPLIT) {
        const int w = blockIdx.x >> 3;
        n0   = (blockIdx.x & 7) * 128;
        B    = (w == 0) ? B0 : (w == 1) ? B1 : B2;
        C    = (w == 0) ? C0 : (w == 1) ? C1 : C2;
        bias = (w == 0) ? bias0 : (w == 1) ? bias1 : bias2;
    } else {
        B = B0; C = C0; bias = bias0;
        n0 = blockIdx.x * 128;
    }
    const int m0 = blockIdx.y * 128;

    const int tid  = threadIdx.x;
    const int wid  = tid >> 5;
    const int lane = tid & 31;
    const int wm   = wid >> 2;
    const int wn   = wid & 3;

    const int cr = tid >> 3;
    const int cc = (tid & 7) << 2;
    const uint32_t dstA0 = smem + (uint32_t)((cr * AS_LD + cc) * 4);
    const uint32_t dstB0 = dstA0 + BOFF_B;
    const float* srcA = A + (size_t)(m0 + cr) * lda + cc;
    const float* srcB = B + (size_t)(n0 + cr) * ldb + cc;

    const int ar = (lane & 7) + ((lane >> 3) & 1) * 8;
    const int ac = (lane >> 4) * 4;
    const int br = ((lane >> 4) & 1) * 8 + (lane & 7);
    const int bc = ((lane >> 3) & 1) * 4;
    uint32_t aOff[4], bOff[2];
    #pragma unroll
    for (int mi = 0; mi < 4; mi++)
        aOff[mi] = (uint32_t)(((wm * 64 + mi * 16 + ar) * AS_LD + ac) * 4);
    #pragma unroll
    for (int pi = 0; pi < 2; pi++)
        bOff[pi] = (uint32_t)(((wn * 32 + pi * 16 + br) * AS_LD + bc) * 4)
                   + BOFF_B;

    float acc[4][4][4];
    #pragma unroll
    for (int i = 0; i < 4; i++)
        #pragma unroll
        for (int j = 0; j < 4; j++)
            #pragma unroll
            for (int r = 0; r < 4; r++) acc[i][j][r] = 0.f;

    const int nk = K / BK;
    // ---- prologue: stages 0 and 1 ----
    #pragma unroll
    for (int s = 0; s < 2; s++) {
        #pragma unroll
        for (int i = 0; i < 4; i++) {
            CP_ASYNC16(dstA0 + s * STAGE_B + i * 32 * AS_LD * 4,
                       srcA + (size_t)i * 32 * lda + s * BK);
            CP_ASYNC16(dstB0 + s * STAGE_B + i * 32 * AS_LD * 4,
                       srcB + (size_t)i * 32 * ldb + s * BK);
        }
        CP_COMMIT();
    }

    int cur = 0;
    for (int it = 0; it < nk; it++) {
        CP_WAIT(1);
        __syncthreads();
        // ---- compute stage cur ----
        const uint32_t stA = smem + cur * STAGE_B;
        #pragma unroll
        for (int kk = 0; kk < 4; kk++) {
            const uint32_t kbB = kk * 32;
            uint32_t af[4][4], bfr[2][4];
            #pragma unroll
            for (int mi = 0; mi < 4; mi++) ldsm_x4(af[mi], stA + aOff[mi] + kbB);
            #pragma unroll
            for (int pi = 0; pi < 2; pi++) ldsm_x4(bfr[pi], stA + bOff[pi] + kbB);
            #pragma unroll
            for (int mi = 0; mi < 4; mi++)
                #pragma unroll
                for (int ni = 0; ni < 4; ni++)
                    mma_tf32(acc[mi][ni], af[mi][0], af[mi][1], af[mi][2],
                             af[mi][3], bfr[ni >> 1][(ni & 1) * 2],
                             bfr[ni >> 1][(ni & 1) * 2 + 1]);
        }
        // ---- prefetch k_{it+2} into stage (cur+2)%3 ----
        if (it + 2 < nk) {
            const int st = (cur + 2) % 3;
            const int kn = (it + 2) * BK;
            #pragma unroll
            for (int i = 0; i < 4; i++) {
                CP_ASYNC16(dstA0 + st * STAGE_B + i * 32 * AS_LD * 4,
                           srcA + (size_t)i * 32 * lda + kn);
                CP_ASYNC16(dstB0 + st * STAGE_B + i * 32 * AS_LD * 4,
                           srcB + (size_t)i * 32 * ldb + kn);
            }
        }
        CP_COMMIT();
        cur = (cur + 1) % 3;
    }

    // ---- epilogue ----
    const int lq = lane >> 2, lr = lane & 3;
    #pragma unroll
    for (int mi = 0; mi < 4; mi++) {
        #pragma unroll
        for (int ni = 0; ni < 4; ni++) {
            const int r = m0 + wm * 64 + mi * 16 + lq;
            const int c = n0 + wn * 32 + ni * 8 + lr * 2;
            float2 v0, v1;
            v0.x = acc[mi][ni][0]; v0.y = acc[mi][ni][1];
            v1.x = acc[mi][ni][2]; v1.y = acc[mi][ni][3];
            float2 b2 = *reinterpret_cast<const float2*>(&bias[c]);
            v0.x += b2.x; v0.y += b2.y;
            v1.x += b2.x; v1.y += b2.y;
            if (EPI == 1 || EPI == 3) {
                v0.x = fmaxf(v0.x, 0.f); v0.y = fmaxf(v0.y, 0.f);
                v1.x = fmaxf(v1.x, 0.f); v1.y = fmaxf(v1.y, 0.f);
            }
            if (EPI == 2 || EPI == 3) {
                float2 r0 = *reinterpret_cast<const float2*>(
                    &res[(size_t)r * ldc + c]);
                float2 r1 = *reinterpret_cast<const float2*>(
                    &res[(size_t)(r + 8) * ldc + c]);
                v0.x += r0.x; v0.y += r0.y;
                v1.x += r1.x; v1.y += r1.y;
            }
            *reinterpret_cast<float2*>(&C[(size_t)r * ldc + c])       = v0;
            *reinterpret_cast<float2*>(&C[(size_t)(r + 8) * ldc + c]) = v1;
        }
    }
}

// ---------------------------------------------------------------------------
// Flash attention: double-buffered K/V (cp.async), ldmatrix Q/K fragments,
// P re-fragmented via register shuffles (no smem P buffer).
// Smem: sQ[128][68] + 2 x (sK[128][68] + sV[128][72]) = 178176 B.
// ---------------------------------------------------------------------------
__global__ void __launch_bounds__(256)
flash_kernel(const float* __restrict__ Q, const float* __restrict__ K,
             const float* __restrict__ V, float* __restrict__ Out) {
    extern __shared__ float fsm[];
    float* sQ = fsm;                          // [128][68]
    // stage s: sK = fsm + 8704 + s*17920 ; sV = sK + 8704

    const int bh = blockIdx.y;
    const int bb = bh >> 4;
    const int hh = bh & 15;
    const int q0 = blockIdx.x * 128;
    const size_t base = (size_t)bb * SEQ * FEATS + (size_t)hh * HD;

    const int tid  = threadIdx.x;
    const int wid  = tid >> 5;
    const int lane = tid & 31;
    const int lq   = lane >> 2;
    const int lr   = lane & 3;

    // ---- load Q (scale 1/32), store to sQ ----
    #pragma unroll
    for (int i = 0; i < 8; i++) {
        int id = tid + i * 256;
        int r = id >> 4, c = (id & 15) << 2;
        float4 v = *reinterpret_cast<const float4*>(
            &Q[base + (size_t)(q0 + r) * FEATS + c]);
        v.x *= 0.03125f; v.y *= 0.03125f; v.z *= 0.03125f; v.w *= 0.03125f;
        *reinterpret_cast<float4*>(&sQ[r * 68 + c]) = v;
    }

    // cp.async K/V mapping: 16 rows/pass, 8 passes
    const int kr = tid >> 4;
    const int kc = (tid & 15) << 2;

    // ldmatrix offsets
    const int arow = (lane & 7) + ((lane >> 3) & 1) * 8;
    const int acol = (lane >> 4) * 4;
    const uint32_t qBase = smem_u32(sQ) +
        (uint32_t)(((wid * 16 + arow) * 68 + acol) * 4);
    const int brow = ((lane >> 4) & 1) * 8 + (lane & 7);
    const int bcol = ((lane >> 3) & 1) * 4;

    // shuffle sources for P re-fragmentation
    const int srcA = (lane & 28) | (lr >> 1);
    const int srcB = srcA + 2;
    const bool sel = (lr & 1);

    float oacc[8][4];
    #pragma unroll
    for (int i = 0; i < 8; i++)
        #pragma unroll
        for (int r = 0; r < 4; r++) oacc[i][r] = 0.f;
    float m0 = -1e30f, m1 = -1e30f, l0 = 0.f, l1 = 0.f;

    // ---- prologue: KV tile 0 into stage 0 ----
    {
        float* sK0 = fsm + 8704;
        float* sV0 = sK0 + 8704;
        const float* srcK = &K[base + (size_t)kr * FEATS + kc];
        const float* srcV = &V[base + (size_t)kr * FEATS + kc];
        const uint32_t dK = smem_u32(&sK0[kr * 68 + kc]);
        const uint32_t dV = smem_u32(&sV0[kr * 72 + kc]);
        #pragma unroll
        for (int i = 0; i < 8; i++) {
            CP_ASYNC16(dK + i * 16 * 68 * 4, srcK + (size_t)i * 16 * FEATS);
            CP_ASYNC16(dV + i * 16 * 72 * 4, srcV + (size_t)i * 16 * FEATS);
        }
        CP_COMMIT();
    }

    for (int t = 0; t < SEQ / 128; t++) {
        __syncthreads();   // all warps done reading stage (t+1)&1 (tile t-1)
        if (t + 1 < SEQ / 128) {
            float* sKn = fsm + 8704 + ((t + 1) & 1) * 17920;
            float* sVn = sKn + 8704;
            const int kv = (t + 1) * 128;
            const float* srcK = &K[base + (size_t)(kv + kr) * FEATS + kc];
            const float* srcV = &V[base + (size_t)(kv + kr) * FEATS + kc];
            const uint32_t dK = smem_u32(&sKn[kr * 68 + kc]);
            const uint32_t dV = smem_u32(&sVn[kr * 72 + kc]);
            #pragma unroll
            for (int i = 0; i < 8; i++) {
                CP_ASYNC16(dK + i * 16 * 68 * 4, srcK + (size_t)i * 16 * FEATS);
                CP_ASYNC16(dV + i * 16 * 72 * 4, srcV + (size_t)i * 16 * FEATS);
            }
        }
        CP_COMMIT();
        CP_WAIT(1);
        __syncthreads();   // tile t data visible

        float* sK = fsm + 8704 + (t & 1) * 17920;
        float* sV = sK + 8704;
        const uint32_t kB = smem_u32(sK);

        // ---- S = Q K^T (warp: 16 x 128) ----
        float sacc[16][4];
        #pragma unroll
        for (int i = 0; i < 16; i++)
            #pragma unroll
            for (int r = 0; r < 4; r++) sacc[i][r] = 0.f;

        #pragma unroll
        for (int kk = 0; kk < 8; kk++) {
            uint32_t aq[4];
            ldsm_x4(aq, qBase + kk * 32);
            #pragma unroll
            for (int pi = 0; pi < 8; pi++) {
                uint32_t bk4[4];
                ldsm_x4(bk4, kB + (uint32_t)(((pi * 16 + brow) * 68 + bcol) * 4)
                              + kk * 32);
                mma_tf32(sacc[2 * pi    ], aq[0], aq[1], aq[2], aq[3],
                         bk4[0], bk4[1]);
                mma_tf32(sacc[2 * pi + 1], aq[0], aq[1], aq[2], aq[3],
                         bk4[2], bk4[3]);
            }
        }

        // ---- online softmax (exp in place) ----
        float mt0 = -1e30f, mt1 = -1e30f;
        #pragma unroll
        for (int ni = 0; ni < 16; ni++) {
            mt0 = fmaxf(mt0, fmaxf(sacc[ni][0], sacc[ni][1]));
            mt1 = fmaxf(mt1, fmaxf(sacc[ni][2], sacc[ni][3]));
        }
        mt0 = fmaxf(mt0, __shfl_xor_sync(0xffffffffu, mt0, 1));
        mt0 = fmaxf(mt0, __shfl_xor_sync(0xffffffffu, mt0, 2));
        mt1 = fmaxf(mt1, __shfl_xor_sync(0xffffffffu, mt1, 1));
        mt1 = fmaxf(mt1, __shfl_xor_sync(0xffffffffu, mt1, 2));

        const float mn0 = fmaxf(m0, mt0), mn1 = fmaxf(m1, mt1);
        const float al0 = __expf(m0 - mn0), al1 = __expf(m1 - mn1);
        float s0 = 0.f, s1 = 0.f;
        #pragma unroll
        for (int ni = 0; ni < 16; ni++) {
            sacc[ni][0] = __expf(sacc[ni][0] - mn0);
            sacc[ni][1] = __expf(sacc[ni][1] - mn0);
            sacc[ni][2] = __expf(sacc[ni][2] - mn1);
            sacc[ni][3] = __expf(sacc[ni][3] - mn1);
            s0 += sacc[ni][0] + sacc[ni][1];
            s1 += sacc[ni][2] + sacc[ni][3];
        }
        s0 += __shfl_xor_sync(0xffffffffu, s0, 1);
        s0 += __shfl_xor_sync(0xffffffffu, s0, 2);
        s1 += __shfl_xor_sync(0xffffffffu, s1, 1);
        s1 += __shfl_xor_sync(0xffffffffu, s1, 2);
        l0 = l0 * al0 + s0; l1 = l1 * al1 + s1;
        m0 = mn0; m1 = mn1;
        #pragma unroll
        for (int oni = 0; oni < 8; oni++) {
            oacc[oni][0] *= al0; oacc[oni][1] *= al0;
            oacc[oni][2] *= al1; oacc[oni][3] *= al1;
        }

        // ---- O += P V : re-fragment P via shuffles ----
        #pragma unroll
        for (int kk = 0; kk < 16; kk++) {
            float v0, v1, a0f, a1f, a2f, a3f;
            v0 = __shfl_sync(0xffffffffu, sacc[kk][0], srcA);
            v1 = __shfl_sync(0xffffffffu, sacc[kk][1], srcA);
            a0f = sel ? v1 : v0;
            v0 = __shfl_sync(0xffffffffu, sacc[kk][0], srcB);
            v1 = __shfl_sync(0xffffffffu, sacc[kk][1], srcB);
            a2f = sel ? v1 : v0;
            v0 = __shfl_sync(0xffffffffu, sacc[kk][2], srcA);
            v1 = __shfl_sync(0xffffffffu, sacc[kk][3], srcA);
            a1f = sel ? v1 : v0;
            v0 = __shfl_sync(0xffffffffu, sacc[kk][2], srcB);
            v1 = __shfl_sync(0xffffffffu, sacc[kk][3], srcB);
            a3f = sel ? v1 : v0;
            const uint32_t a0 = __float_as_uint(a0f);
            const uint32_t a1 = __float_as_uint(a1f);
            const uint32_t a2 = __float_as_uint(a2f);
            const uint32_t a3 = __float_as_uint(a3f);
            const int kb = kk * 8;
            #pragma unroll
            for (int oni = 0; oni < 8; oni++) {
                const int n = oni * 8 + lq;
                uint32_t b0 = __float_as_uint(sV[(kb + lr    ) * 72 + n]);
                uint32_t b1 = __float_as_uint(sV[(kb + lr + 4) * 72 + n]);
                mma_tf32(oacc[oni], a0, a1, a2, a3, b0, b1);
            }
        }
    }

    // ---- epilogue ----
    const float inv0 = __fdividef(1.f, l0);
    const float inv1 = __fdividef(1.f, l1);
    const int mrow = wid * 16 + lq;
    const size_t r0 = base + (size_t)(q0 + mrow) * FEATS;
    const size_t r1 = r0 + (size_t)8 * FEATS;
    #pragma unroll
    for (int oni = 0; oni < 8; oni++) {
        const int c = oni * 8 + lr * 2;
        *reinterpret_cast<float2*>(&Out[r0 + c]) =
            make_float2(oacc[oni][0] * inv0, oacc[oni][1] * inv0);
        *reinterpret_cast<float2*>(&Out[r1 + c]) =
            make_float2(oacc[oni][2] * inv1, oacc[oni][3] * inv1);
    }
}

// ---------------------------------------------------------------------------
#define GEMM_SMEM  (3 * 2 * 128 * (BK + 4) * 4)            // 110592 B
#define FLASH_SMEM ((8704 + 2 * (8704 + 9216)) * 4)        // 178176 B

extern "C" void kernel_launch(void* const* d_in, const int* in_sizes, int n_in,
                              void* d_out, int out_size) {
    (void)in_sizes; (void)n_in; (void)out_size;
    const float* x    = (const float*)d_in[0];
    const float* ln1g = (const float*)d_in[1];
    const float* ln1b = (const float*)d_in[2];
    const float* wq   = (const float*)d_in[3];
    const float* bq   = (const float*)d_in[4];
    const float* wk   = (const float*)d_in[5];
    const float* bk   = (const float*)d_in[6];
    const float* wv   = (const float*)d_in[7];
    const float* bv   = (const float*)d_in[8];
    const float* wo   = (const float*)d_in[9];
    const float* bo   = (const float*)d_in[10];
    const float* ln2g = (const float*)d_in[11];
    const float* ln2b = (const float*)d_in[12];
    const float* w1   = (const float*)d_in[13];
    const float* b1   = (const float*)d_in[14];
    const float* w2   = (const float*)d_in[15];
    const float* b2   = (const float*)d_in[16];
    float* out = (float*)d_out;

    float *h1, *q, *k, *v, *attn, *out1, *h2, *m1;
    cudaGetSymbolAddress((void**)&h1,   g_h1);
    cudaGetSymbolAddress((void**)&q,    g_q);
    cudaGetSymbolAddress((void**)&k,    g_k);
    cudaGetSymbolAddress((void**)&v,    g_v);
    cudaGetSymbolAddress((void**)&attn, g_attn);
    cudaGetSymbolAddress((void**)&out1, g_out1);
    cudaGetSymbolAddress((void**)&h2,   g_h2);
    cudaGetSymbolAddress((void**)&m1,   g_m1);

    cudaFuncSetAttribute(mma_gemm<0,true>,  cudaFuncAttributeMaxDynamicSharedMemorySize, GEMM_SMEM);
    cudaFuncSetAttribute(mma_gemm<1,false>, cudaFuncAttributeMaxDynamicSharedMemorySize, GEMM_SMEM);
    cudaFuncSetAttribute(mma_gemm<2,false>, cudaFuncAttributeMaxDynamicSharedMemorySize, GEMM_SMEM);
    cudaFuncSetAttribute(mma_gemm<3,false>, cudaFuncAttributeMaxDynamicSharedMemorySize, GEMM_SMEM);
    cudaFuncSetAttribute(flash_kernel, cudaFuncAttributeMaxDynamicSharedMemorySize, FLASH_SMEM);

    // 1) LN1
    ln_kernel<<<TOK, 256>>>(x, ln1g, ln1b, h1);

    // 2) fused Q/K/V projections
    {
        dim3 grid(24, TOK / 128);
        mma_gemm<0,true><<<grid, 256, GEMM_SMEM>>>(
            h1, wq, wk, wv, q, k, v, bq, bk, bv, nullptr,
            FEATS, FEATS, FEATS, FEATS);
    }

    // 3) fused attention
    {
        dim3 grid(SEQ / 128, BATCH * HEADS);
        flash_kernel<<<grid, 256, FLASH_SMEM>>>(q, k, v, attn);
    }

    // 4) O projection + residual
    {
        dim3 grid(FEATS / 128, TOK / 128);
        mma_gemm<2,false><<<grid, 256, GEMM_SMEM>>>(
            attn, wo, nullptr, nullptr, out1, nullptr, nullptr,
            bo, nullptr, nullptr, x, FEATS, FEATS, FEATS, FEATS);
    }

    // 5) LN2
    ln_kernel<<<TOK, 256>>>(out1, ln2g, ln2b, h2);

    // 6) MLP up: relu(h2 @ w1^T + b1)
    {
        dim3 grid(HIDDEN / 128, TOK / 128);
        mma_gemm<1,false><<<grid, 256, GEMM_SMEM>>>(
            h2, w1, nullptr, nullptr, m1, nullptr, nullptr,
            b1, nullptr, nullptr, nullptr, FEATS, FEATS, FEATS, HIDDEN);
    }

    // 7) MLP down: relu(m1 @ w2^T + b2) + out1
    {
        dim3 grid(FEATS / 128, TOK / 128);
        mma_gemm<3,false><<<grid, 256, GEMM_SMEM>>>(
            m1, w2, nullptr, nullptr, out, nullptr, nullptr,
            b2, nullptr, nullptr, out1, HIDDEN, HIDDEN, HIDDEN, FEATS);
    }
}

// round 7
// speedup vs baseline: 6.6854x; 1.7897x over previous
#include <cuda_runtime.h>
#include <cuda_fp16.h>
#include <cstdint>
#include <cstddef>

#define FEATS  1024
#define SEQ    2048
#define BATCH  2
#define TOK    (BATCH * SEQ)     // 4096
#define HEADS  16
#define HD     64
#define HIDDEN 4096
#define LN_EPS 1e-5f

// ---- scratch ----
__device__ __half g_h1h [(size_t)TOK * FEATS];
__device__ __half g_qh  [(size_t)TOK * FEATS];
__device__ __half g_kh  [(size_t)TOK * FEATS];
__device__ __half g_vh  [(size_t)TOK * FEATS];
__device__ __half g_atth[(size_t)TOK * FEATS];
__device__ float  g_out1[(size_t)TOK * FEATS];
__device__ __half g_h2h [(size_t)TOK * FEATS];
__device__ __half g_m1h [(size_t)TOK * HIDDEN];
__device__ __half g_wqh [(size_t)FEATS * FEATS];
__device__ __half g_wkh [(size_t)FEATS * FEATS];
__device__ __half g_wvh [(size_t)FEATS * FEATS];
__device__ __half g_woh [(size_t)FEATS * FEATS];
__device__ __half g_w1h [(size_t)HIDDEN * FEATS];
__device__ __half g_w2h [(size_t)FEATS * HIDDEN];

// ---------------------------------------------------------------------------
__device__ __forceinline__ uint32_t smem_u32(const void* p) {
    return (uint32_t)__cvta_generic_to_shared(p);
}
#define CP_ASYNC16(dst, src) \
    asm volatile("cp.async.cg.shared.global [%0], [%1], 16;\n" \
                 :: "r"(dst), "l"(src))
#define CP_COMMIT() asm volatile("cp.async.commit_group;\n")
#define CP_WAIT(N)  asm volatile("cp.async.wait_group %0;\n" :: "n"(N))

__device__ __forceinline__ void mma_f16(float c[4],
                                        uint32_t a0, uint32_t a1,
                                        uint32_t a2, uint32_t a3,
                                        uint32_t b0, uint32_t b1) {
    asm volatile(
        "mma.sync.aligned.m16n8k16.row.col.f32.f16.f16.f32 "
        "{%0,%1,%2,%3}, {%4,%5,%6,%7}, {%8,%9}, {%0,%1,%2,%3};\n"
        : "+f"(c[0]), "+f"(c[1]), "+f"(c[2]), "+f"(c[3])
        : "r"(a0), "r"(a1), "r"(a2), "r"(a3), "r"(b0), "r"(b1));
}
__device__ __forceinline__ void ldsm_x4(uint32_t r[4], uint32_t addr) {
    asm volatile("ldmatrix.sync.aligned.m8n8.x4.shared.b16 {%0,%1,%2,%3}, [%4];"
                 : "=r"(r[0]), "=r"(r[1]), "=r"(r[2]), "=r"(r[3]) : "r"(addr));
}
__device__ __forceinline__ void ldsm_x4_t(uint32_t r[4], uint32_t addr) {
    asm volatile("ldmatrix.sync.aligned.m8n8.x4.trans.shared.b16 {%0,%1,%2,%3}, [%4];"
                 : "=r"(r[0]), "=r"(r[1]), "=r"(r[2]), "=r"(r[3]) : "r"(addr));
}
__device__ __forceinline__ uint32_t pack_h2(float lo, float hi) {
    __half2 h = __floats2half2_rn(lo, hi);
    return *reinterpret_cast<uint32_t*>(&h);
}
__device__ __forceinline__ uint32_t swz(int row, int c16) {
    return (uint32_t)(row * 128 + ((c16 ^ (row & 7)) << 4));
}

// ---------------------------------------------------------------------------
__global__ void cvt_kernel(const float* __restrict__ src,
                           __half* __restrict__ dst, int n4) {
    int i = blockIdx.x * blockDim.x + threadIdx.x;
    if (i < n4) {
        float4 v = reinterpret_cast<const float4*>(src)[i];
        __half2* d = reinterpret_cast<__half2*>(dst) + i * 2;
        d[0] = __floats2half2_rn(v.x, v.y);
        d[1] = __floats2half2_rn(v.z, v.w);
    }
}

// ---------------------------------------------------------------------------
__global__ void ln_kernel(const float* __restrict__ x,
                          const float* __restrict__ g,
                          const float* __restrict__ b,
                          __half* __restrict__ out) {
    const size_t row = blockIdx.x;
    const int t = threadIdx.x;
    float4 v = reinterpret_cast<const float4*>(x + row * FEATS)[t];

    float s  = v.x + v.y + v.z + v.w;
    float ss = v.x * v.x + v.y * v.y + v.z * v.z + v.w * v.w;

    __shared__ float smS[8], smQ[8];
    #pragma unroll
    for (int o = 16; o; o >>= 1) {
        s  += __shfl_xor_sync(0xffffffffu, s,  o);
        ss += __shfl_xor_sync(0xffffffffu, ss, o);
    }
    if ((t & 31) == 0) { smS[t >> 5] = s; smQ[t >> 5] = ss; }
    __syncthreads();
    float tS = 0.f, tQ = 0.f;
    #pragma unroll
    for (int i = 0; i < 8; i++) { tS += smS[i]; tQ += smQ[i]; }

    const float mean = tS * (1.0f / FEATS);
    const float var  = tQ * (1.0f / FEATS) - mean * mean;
    const float rstd = rsqrtf(var + LN_EPS);

    float4 gg = reinterpret_cast<const float4*>(g)[t];
    float4 bb = reinterpret_cast<const float4*>(b)[t];
    __half2* po = reinterpret_cast<__half2*>(out + row * FEATS) + t * 2;
    po[0] = __floats2half2_rn((v.x - mean) * rstd * gg.x + bb.x,
                              (v.y - mean) * rstd * gg.y + bb.y);
    po[1] = __floats2half2_rn((v.z - mean) * rstd * gg.z + bb.z,
                              (v.w - mean) * rstd * gg.w + bb.w);
}

// ---------------------------------------------------------------------------
// FP16 NT GEMM: BM=BN=128, BK=64, 3-stage cp.async ring, SW128 swizzle.
// ---------------------------------------------------------------------------
template<int EPI, bool SPLIT, bool OUT_HALF>
__global__ void __launch_bounds__(256, 2)
h_gemm(const __half* __restrict__ A,
       const __half* __restrict__ B0, const __half* __restrict__ B1,
       const __half* __restrict__ B2,
       void* __restrict__ C0, void* __restrict__ C1, void* __restrict__ C2,
       const float* __restrict__ bias0, const float* __restrict__ bias1,
       const float* __restrict__ bias2,
       const float* __restrict__ res,
       int K, int lda, int ldb, int ldc) {
    constexpr int STAGE_B = 32768;
    extern __shared__ __half gsm[];
    const uint32_t smem = smem_u32(gsm);

    const __half* Bp; void* Cv; const float* bias; int n0;
    if (SPLIT) {
        const int w = blockIdx.x >> 3;
        n0   = (blockIdx.x & 7) * 128;
        Bp   = (w == 0) ? B0 : (w == 1) ? B1 : B2;
        Cv   = (w == 0) ? C0 : (w == 1) ? C1 : C2;
        bias = (w == 0) ? bias0 : (w == 1) ? bias1 : bias2;
    } else {
        Bp = B0; Cv = C0; bias = bias0;
        n0 = blockIdx.x * 128;
    }
    const int m0 = blockIdx.y * 128;

    const int tid  = threadIdx.x;
    const int wid  = tid >> 5;
    const int lane = tid & 31;
    const int wm   = wid >> 2;
    const int wn   = wid & 3;
    const int cr   = tid >> 3;
    const int cc   = tid & 7;
    const int lrow = lane & 15;
    const int lchk = lane >> 4;

    float acc[4][4][4];
    #pragma unroll
    for (int i = 0; i < 4; i++)
        #pragma unroll
        for (int j = 0; j < 4; j++)
            #pragma unroll
            for (int r = 0; r < 4; r++) acc[i][j][r] = 0.f;

    auto stage = [&](int buf, int k0) {
        const uint32_t base = smem + buf * STAGE_B;
        #pragma unroll
        for (int i = 0; i < 4; i++) {
            const int row = cr + i * 32;
            CP_ASYNC16(base + swz(row, cc),
                       A + (size_t)(m0 + row) * lda + k0 + cc * 8);
            CP_ASYNC16(base + 16384 + swz(row, cc),
                       Bp + (size_t)(n0 + row) * ldb + k0 + cc * 8);
        }
    };

    const int nk = K / 64;
    stage(0, 0);  CP_COMMIT();
    stage(1, 64); CP_COMMIT();

    int cur = 0;
    for (int it = 0; it < nk; it++) {
        CP_WAIT(1);
        __syncthreads();
        const uint32_t aB = smem + cur * STAGE_B;
        const uint32_t bB = aB + 16384;
        #pragma unroll
        for (int kk = 0; kk < 4; kk++) {
            uint32_t af[4][4], bf[2][4];
            #pragma unroll
            for (int mi = 0; mi < 4; mi++)
                ldsm_x4(af[mi], aB + swz(wm * 64 + mi * 16 + lrow,
                                         kk * 2 + lchk));
            #pragma unroll
            for (int pi = 0; pi < 2; pi++)
                ldsm_x4(bf[pi], bB + swz(wn * 32 + pi * 16 + lrow,
                                         kk * 2 + lchk));
            #pragma unroll
            for (int mi = 0; mi < 4; mi++)
                #pragma unroll
                for (int ni = 0; ni < 4; ni++) {
                    const int pi = ni >> 1, od = ni & 1;
                    mma_f16(acc[mi][ni], af[mi][0], af[mi][1], af[mi][2],
                            af[mi][3], bf[pi][od], bf[pi][od + 2]);
                }
        }
        if (it + 2 < nk) stage((cur + 2) % 3, (it + 2) * 64);
        CP_COMMIT();
        cur = (cur + 1) % 3;
    }

    const int lq = lane >> 2, lr = lane & 3;
    #pragma unroll
    for (int mi = 0; mi < 4; mi++) {
        #pragma unroll
        for (int ni = 0; ni < 4; ni++) {
            const int r = m0 + wm * 64 + mi * 16 + lq;
            const int c = n0 + wn * 32 + ni * 8 + lr * 2;
            float2 v0, v1;
            v0.x = acc[mi][ni][0]; v0.y = acc[mi][ni][1];
            v1.x = acc[mi][ni][2]; v1.y = acc[mi][ni][3];
            float2 b2 = *reinterpret_cast<const float2*>(&bias[c]);
            v0.x += b2.x; v0.y += b2.y;
            v1.x += b2.x; v1.y += b2.y;
            if (EPI == 1 || EPI == 3) {
                v0.x = fmaxf(v0.x, 0.f); v0.y = fmaxf(v0.y, 0.f);
                v1.x = fmaxf(v1.x, 0.f); v1.y = fmaxf(v1.y, 0.f);
            }
            if (EPI == 2 || EPI == 3) {
                float2 r0 = *reinterpret_cast<const float2*>(
                    &res[(size_t)r * ldc + c]);
                float2 r1 = *reinterpret_cast<const float2*>(
                    &res[(size_t)(r + 8) * ldc + c]);
                v0.x += r0.x; v0.y += r0.y;
                v1.x += r1.x; v1.y += r1.y;
            }
            if (OUT_HALF) {
                __half* Ch = (__half*)Cv;
                *reinterpret_cast<__half2*>(&Ch[(size_t)r * ldc + c]) =
                    __floats2half2_rn(v0.x, v0.y);
                *reinterpret_cast<__half2*>(&Ch[(size_t)(r + 8) * ldc + c]) =
                    __floats2half2_rn(v1.x, v1.y);
            } else {
                float* Cf = (float*)Cv;
                *reinterpret_cast<float2*>(&Cf[(size_t)r * ldc + c])       = v0;
                *reinterpret_cast<float2*>(&Cf[(size_t)(r + 8) * ldc + c]) = v1;
            }
        }
    }
}

// ---------------------------------------------------------------------------
// FP16 flash attention. smem 80KB: sQ + 2 x (sK + sV), SW128 swizzled.
// ---------------------------------------------------------------------------
__global__ void __launch_bounds__(256)
flash_kernel(const __half* __restrict__ Q, const __half* __restrict__ K,
             const __half* __restrict__ V, __half* __restrict__ Out) {
    extern __shared__ __half fsm[];
    const uint32_t sQ = smem_u32(fsm);

    const int bh = blockIdx.y;
    const int bb = bh >> 4;
    const int hh = bh & 15;
    const int q0 = blockIdx.x * 128;
    const size_t base = (size_t)bb * SEQ * FEATS + (size_t)hh * HD;

    const int tid  = threadIdx.x;
    const int wid  = tid >> 5;
    const int lane = tid & 31;
    const int lq   = lane >> 2;
    const int lr   = lane & 3;
    const int lrow = lane & 15;
    const int lchk = lane >> 4;
    const int cr   = tid >> 3;
    const int cc   = tid & 7;
    const int vrow = (lane & 7) + ((lane >> 3) & 1) * 8;  // trans ldsm row

    #pragma unroll
    for (int i = 0; i < 4; i++) {
        const int row = cr + i * 32;
        CP_ASYNC16(sQ + swz(row, cc),
                   Q + base + (size_t)(q0 + row) * FEATS + cc * 8);
    }
    CP_COMMIT();

    auto stageKV = [&](int buf, int kv0) {
        const uint32_t kb = sQ + 16384 + buf * 32768;
        #pragma unroll
        for (int i = 0; i < 4; i++) {
            const int row = cr + i * 32;
            CP_ASYNC16(kb + swz(row, cc),
                       K + base + (size_t)(kv0 + row) * FEATS + cc * 8);
            CP_ASYNC16(kb + 16384 + swz(row, cc),
                       V + base + (size_t)(kv0 + row) * FEATS + cc * 8);
        }
    };
    stageKV(0, 0);
    CP_COMMIT();

    float oacc[8][4];
    #pragma unroll
    for (int i = 0; i < 8; i++)
        #pragma unroll
        for (int r = 0; r < 4; r++) oacc[i][r] = 0.f;
    float m0 = -1e30f, m1 = -1e30f, l0 = 0.f, l1 = 0.f;

    for (int t = 0; t < SEQ / 128; t++) {
        __syncthreads();
        if (t + 1 < SEQ / 128) stageKV((t + 1) & 1, (t + 1) * 128);
        CP_COMMIT();
        CP_WAIT(1);
        __syncthreads();

        const uint32_t kB = sQ + 16384 + (t & 1) * 32768;
        const uint32_t vB = kB + 16384;

        float sacc[16][4];
        #pragma unroll
        for (int i = 0; i < 16; i++)
            #pragma unroll
            for (int r = 0; r < 4; r++) sacc[i][r] = 0.f;

        #pragma unroll
        for (int kk = 0; kk < 4; kk++) {
            uint32_t aq[4];
            ldsm_x4(aq, sQ + swz(wid * 16 + lrow, kk * 2 + lchk));
            #pragma unroll
            for (int pi = 0; pi < 8; pi++) {
                uint32_t bk[4];
                ldsm_x4(bk, kB + swz(pi * 16 + lrow, kk * 2 + lchk));
                mma_f16(sacc[2 * pi    ], aq[0], aq[1], aq[2], aq[3],
                        bk[0], bk[2]);
                mma_f16(sacc[2 * pi + 1], aq[0], aq[1], aq[2], aq[3],
                        bk[1], bk[3]);
            }
        }

        float mt0 = -1e30f, mt1 = -1e30f;
        #pragma unroll
        for (int ni = 0; ni < 16; ni++) {
            sacc[ni][0] *= 0.03125f; sacc[ni][1] *= 0.03125f;
            sacc[ni][2] *= 0.03125f; sacc[ni][3] *= 0.03125f;
            mt0 = fmaxf(mt0, fmaxf(sacc[ni][0], sacc[ni][1]));
            mt1 = fmaxf(mt1, fmaxf(sacc[ni][2], sacc[ni][3]));
        }
        mt0 = fmaxf(mt0, __shfl_xor_sync(0xffffffffu, mt0, 1));
        mt0 = fmaxf(mt0, __shfl_xor_sync(0xffffffffu, mt0, 2));
        mt1 = fmaxf(mt1, __shfl_xor_sync(0xffffffffu, mt1, 1));
        mt1 = fmaxf(mt1, __shfl_xor_sync(0xffffffffu, mt1, 2));

        const float mn0 = fmaxf(m0, mt0), mn1 = fmaxf(m1, mt1);
        const float al0 = __expf(m0 - mn0), al1 = __expf(m1 - mn1);
        float s0 = 0.f, s1 = 0.f;
        #pragma unroll
        for (int ni = 0; ni < 16; ni++) {
            sacc[ni][0] = __expf(sacc[ni][0] - mn0);
            sacc[ni][1] = __expf(sacc[ni][1] - mn0);
            sacc[ni][2] = __expf(sacc[ni][2] - mn1);
            sacc[ni][3] = __expf(sacc[ni][3] - mn1);
            s0 += sacc[ni][0] + sacc[ni][1];
            s1 += sacc[ni][2] + sacc[ni][3];
        }
        s0 += __shfl_xor_sync(0xffffffffu, s0, 1);
        s0 += __shfl_xor_sync(0xffffffffu, s0, 2);
        s1 += __shfl_xor_sync(0xffffffffu, s1, 1);
        s1 += __shfl_xor_sync(0xffffffffu, s1, 2);
        l0 = l0 * al0 + s0; l1 = l1 * al1 + s1;
        m0 = mn0; m1 = mn1;
        #pragma unroll
        for (int oni = 0; oni < 8; oni++) {
            oacc[oni][0] *= al0; oacc[oni][1] *= al0;
            oacc[oni][2] *= al1; oacc[oni][3] *= al1;
        }

        // ---- O += P V : fp16 acc->A frag needs no shuffles ----
        #pragma unroll
        for (int kk = 0; kk < 8; kk++) {
            const uint32_t a0 = pack_h2(sacc[2 * kk][0],     sacc[2 * kk][1]);
            const uint32_t a1 = pack_h2(sacc[2 * kk][2],     sacc[2 * kk][3]);
            const uint32_t a2 = pack_h2(sacc[2 * kk + 1][0], sacc[2 * kk + 1][1]);
            const uint32_t a3 = pack_h2(sacc[2 * kk + 1][2], sacc[2 * kk + 1][3]);
            #pragma unroll
            for (int nb = 0; nb < 4; nb++) {       // hd 16-blocks
                uint32_t bv[4];
                ldsm_x4_t(bv, vB + swz(kk * 16 + vrow, nb * 2 + lchk));
                mma_f16(oacc[2 * nb    ], a0, a1, a2, a3, bv[0], bv[1]);
                mma_f16(oacc[2 * nb + 1], a0, a1, a2, a3, bv[2], bv[3]);
            }
        }
    }

    const float inv0 = __fdividef(1.f, l0);
    const float inv1 = __fdividef(1.f, l1);
    const int mrow = wid * 16 + lq;
    __half* o0 = Out + base + (size_t)(q0 + mrow) * FEATS;
    __half* o1 = o0 + (size_t)8 * FEATS;
    #pragma unroll
    for (int oni = 0; oni < 8; oni++) {
        const int c = oni * 8 + lr * 2;
        *reinterpret_cast<__half2*>(o0 + c) =
            __floats2half2_rn(oacc[oni][0] * inv0, oacc[oni][1] * inv0);
        *reinterpret_cast<__half2*>(o1 + c) =
            __floats2half2_rn(oacc[oni][2] * inv1, oacc[oni][3] * inv1);
    }
}

// ---------------------------------------------------------------------------
#define GEMM_SMEM  (3 * 32768)      // 98304 B
#define FLASH_SMEM (5 * 16384)      // 81920 B

extern "C" void kernel_launch(void* const* d_in, const int* in_sizes, int n_in,
                              void* d_out, int out_size) {
    (void)in_sizes; (void)n_in; (void)out_size;
    const float* x    = (const float*)d_in[0];
    const float* ln1g = (const float*)d_in[1];
    const float* ln1b = (const float*)d_in[2];
    const float* wq   = (const float*)d_in[3];
    const float* bq   = (const float*)d_in[4];
    const float* wk   = (const float*)d_in[5];
    const float* bk   = (const float*)d_in[6];
    const float* wv   = (const float*)d_in[7];
    const float* bv   = (const float*)d_in[8];
    const float* wo   = (const float*)d_in[9];
    const float* bo   = (const float*)d_in[10];
    const float* ln2g = (const float*)d_in[11];
    const float* ln2b = (const float*)d_in[12];
    const float* w1   = (const float*)d_in[13];
    const float* b1   = (const float*)d_in[14];
    const float* w2   = (const float*)d_in[15];
    const float* b2   = (const float*)d_in[16];
    float* out = (float*)d_out;

    __half *h1, *q, *k, *v, *att, *h2, *m1;
    __half *wqh, *wkh, *wvh, *woh, *w1h, *w2h;
    float *out1;
    cudaGetSymbolAddress((void**)&h1,   g_h1h);
    cudaGetSymbolAddress((void**)&q,    g_qh);
    cudaGetSymbolAddress((void**)&k,    g_kh);
    cudaGetSymbolAddress((void**)&v,    g_vh);
    cudaGetSymbolAddress((void**)&att,  g_atth);
    cudaGetSymbolAddress((void**)&out1, g_out1);
    cudaGetSymbolAddress((void**)&h2,   g_h2h);
    cudaGetSymbolAddress((void**)&m1,   g_m1h);
    cudaGetSymbolAddress((void**)&wqh,  g_wqh);
    cudaGetSymbolAddress((void**)&wkh,  g_wkh);
    cudaGetSymbolAddress((void**)&wvh,  g_wvh);
    cudaGetSymbolAddress((void**)&woh,  g_woh);
    cudaGetSymbolAddress((void**)&w1h,  g_w1h);
    cudaGetSymbolAddress((void**)&w2h,  g_w2h);

    cudaFuncSetAttribute(h_gemm<0,true,true>,   cudaFuncAttributeMaxDynamicSharedMemorySize, GEMM_SMEM);
    cudaFuncSetAttribute(h_gemm<2,false,false>, cudaFuncAttributeMaxDynamicSharedMemorySize, GEMM_SMEM);
    cudaFuncSetAttribute(h_gemm<1,false,true>,  cudaFuncAttributeMaxDynamicSharedMemorySize, GEMM_SMEM);
    cudaFuncSetAttribute(h_gemm<3,false,false>, cudaFuncAttributeMaxDynamicSharedMemorySize, GEMM_SMEM);
    cudaFuncSetAttribute(flash_kernel, cudaFuncAttributeMaxDynamicSharedMemorySize, FLASH_SMEM);

    // 0) weight conversions (fp32 -> fp16)
    cvt_kernel<<<FEATS * FEATS / 4 / 256, 256>>>(wq, wqh, FEATS * FEATS / 4);
    cvt_kernel<<<FEATS * FEATS / 4 / 256, 256>>>(wk, wkh, FEATS * FEATS / 4);
    cvt_kernel<<<FEATS * FEATS / 4 / 256, 256>>>(wv, wvh, FEATS * FEATS / 4);
    cvt_kernel<<<FEATS * FEATS / 4 / 256, 256>>>(wo, woh, FEATS * FEATS / 4);
    cvt_kernel<<<HIDDEN * FEATS / 4 / 256, 256>>>(w1, w1h, HIDDEN * FEATS / 4);
    cvt_kernel<<<HIDDEN * FEATS / 4 / 256, 256>>>(w2, w2h, HIDDEN * FEATS / 4);

    // 1) LN1 -> fp16
    ln_kernel<<<TOK, 256>>>(x, ln1g, ln1b, h1);

    // 2) fused Q/K/V projections (fp16 out)
    {
        dim3 grid(24, TOK / 128);
        h_gemm<0,true,true><<<grid, 256, GEMM_SMEM>>>(
            h1, wqh, wkh, wvh, q, k, v, bq, bk, bv, nullptr,
            FEATS, FEATS, FEATS, FEATS);
    }

    // 3) flash attention (fp16 out)
    {
        dim3 grid(SEQ / 128, BATCH * HEADS);
        flash_kernel<<<grid, 256, FLASH_SMEM>>>(q, k, v, att);
    }

    // 4) O projection + residual x -> out1 (fp32)
    {
        dim3 grid(FEATS / 128, TOK / 128);
        h_gemm<2,false,false><<<grid, 256, GEMM_SMEM>>>(
            att, woh, nullptr, nullptr, out1, nullptr, nullptr,
            bo, nullptr, nullptr, x, FEATS, FEATS, FEATS, FEATS);
    }

    // 5) LN2 -> fp16
    ln_kernel<<<TOK, 256>>>(out1, ln2g, ln2b, h2);

    // 6) MLP up: relu(h2 @ w1^T + b1) -> m1 (fp16)
    {
        dim3 grid(HIDDEN / 128, TOK / 128);
        h_gemm<1,false,true><<<grid, 256, GEMM_SMEM>>>(
            h2, w1h, nullptr, nullptr, m1, nullptr, nullptr,
            b1, nullptr, nullptr, nullptr, FEATS, FEATS, FEATS, HIDDEN);
    }

    // 7) MLP down: relu(m1 @ w2^T + b2) + out1 -> out (fp32)
    {
        dim3 grid(FEATS / 128, TOK / 128);
        h_gemm<3,false,false><<<grid, 256, GEMM_SMEM>>>(
            m1, w2h, nullptr, nullptr, out, nullptr, nullptr,
            b2, nullptr, nullptr, out1, HIDDEN, HIDDEN, HIDDEN, FEATS);
    }
}

// round 8
// speedup vs baseline: 6.7919x; 1.0159x over previous
#include <cuda_runtime.h>
#include <cuda_fp16.h>
#include <cstdint>
#include <cstddef>

#define FEATS  1024
#define SEQ    2048
#define BATCH  2
#define TOK    (BATCH * SEQ)     // 4096
#define HEADS  16
#define HD     64
#define HIDDEN 4096
#define LN_EPS 1e-5f

// ---- scratch ----
__device__ __half g_h1h [(size_t)TOK * FEATS];
__device__ __half g_qh  [(size_t)TOK * FEATS];
__device__ __half g_kh  [(size_t)TOK * FEATS];
__device__ __half g_vh  [(size_t)TOK * FEATS];
__device__ __half g_atth[(size_t)TOK * FEATS];
__device__ float  g_out1[(size_t)TOK * FEATS];
__device__ __half g_h2h [(size_t)TOK * FEATS];
__device__ __half g_m1h [(size_t)TOK * HIDDEN];
__device__ __half g_wqh [(size_t)FEATS * FEATS];
__device__ __half g_wkh [(size_t)FEATS * FEATS];
__device__ __half g_wvh [(size_t)FEATS * FEATS];
__device__ __half g_woh [(size_t)FEATS * FEATS];
__device__ __half g_w1h [(size_t)HIDDEN * FEATS];
__device__ __half g_w2h [(size_t)FEATS * HIDDEN];

// ---------------------------------------------------------------------------
__device__ __forceinline__ uint32_t smem_u32(const void* p) {
    return (uint32_t)__cvta_generic_to_shared(p);
}
#define CP_ASYNC16(dst, src) \
    asm volatile("cp.async.cg.shared.global [%0], [%1], 16;\n" \
                 :: "r"(dst), "l"(src))
#define CP_COMMIT() asm volatile("cp.async.commit_group;\n")
#define CP_WAIT(N)  asm volatile("cp.async.wait_group %0;\n" :: "n"(N))

__device__ __forceinline__ void mma_f16(float c[4],
                                        uint32_t a0, uint32_t a1,
                                        uint32_t a2, uint32_t a3,
                                        uint32_t b0, uint32_t b1) {
    asm volatile(
        "mma.sync.aligned.m16n8k16.row.col.f32.f16.f16.f32 "
        "{%0,%1,%2,%3}, {%4,%5,%6,%7}, {%8,%9}, {%0,%1,%2,%3};\n"
        : "+f"(c[0]), "+f"(c[1]), "+f"(c[2]), "+f"(c[3])
        : "r"(a0), "r"(a1), "r"(a2), "r"(a3), "r"(b0), "r"(b1));
}
__device__ __forceinline__ void ldsm_x4(uint32_t r[4], uint32_t addr) {
    asm volatile("ldmatrix.sync.aligned.m8n8.x4.shared.b16 {%0,%1,%2,%3}, [%4];"
                 : "=r"(r[0]), "=r"(r[1]), "=r"(r[2]), "=r"(r[3]) : "r"(addr));
}
__device__ __forceinline__ void ldsm_x4_t(uint32_t r[4], uint32_t addr) {
    asm volatile("ldmatrix.sync.aligned.m8n8.x4.trans.shared.b16 {%0,%1,%2,%3}, [%4];"
                 : "=r"(r[0]), "=r"(r[1]), "=r"(r[2]), "=r"(r[3]) : "r"(addr));
}
__device__ __forceinline__ uint32_t pack_h2(float lo, float hi) {
    __half2 h = __floats2half2_rn(lo, hi);
    return *reinterpret_cast<uint32_t*>(&h);
}
__device__ __forceinline__ uint32_t swz(int row, int c16) {
    return (uint32_t)(row * 128 + ((c16 ^ (row & 7)) << 4));
}

// ---------------------------------------------------------------------------
// fused fp32->fp16 weight conversion (all 6 weights, one launch)
// segments (in float4 units): 4 x 262144 (wq,wk,wv,wo), 2 x 1048576 (w1,w2)
// ---------------------------------------------------------------------------
__global__ void cvt_all_kernel(const float* __restrict__ wq,
                               const float* __restrict__ wk,
                               const float* __restrict__ wv,
                               const float* __restrict__ wo,
                               const float* __restrict__ w1,
                               const float* __restrict__ w2,
                               __half* __restrict__ dq, __half* __restrict__ dk,
                               __half* __restrict__ dv, __half* __restrict__ dor,
                               __half* __restrict__ d1, __half* __restrict__ d2) {
    int i = blockIdx.x * blockDim.x + threadIdx.x;
    const float* s; __half* d; int off;
    if (i < 262144)            { s = wq; d = dq;  off = i; }
    else if (i < 524288)       { s = wk; d = dk;  off = i - 262144; }
    else if (i < 786432)       { s = wv; d = dv;  off = i - 524288; }
    else if (i < 1048576)      { s = wo; d = dor; off = i - 786432; }
    else if (i < 2097152)      { s = w1; d = d1;  off = i - 1048576; }
    else                       { s = w2; d = d2;  off = i - 2097152; }
    float4 v = reinterpret_cast<const float4*>(s)[off];
    __half2* p = reinterpret_cast<__half2*>(d) + off * 2;
    p[0] = __floats2half2_rn(v.x, v.y);
    p[1] = __floats2half2_rn(v.z, v.w);
}

// ---------------------------------------------------------------------------
__global__ void ln_kernel(const float* __restrict__ x,
                          const float* __restrict__ g,
                          const float* __restrict__ b,
                          __half* __restrict__ out) {
    const size_t row = blockIdx.x;
    const int t = threadIdx.x;
    float4 v = reinterpret_cast<const float4*>(x + row * FEATS)[t];

    float s  = v.x + v.y + v.z + v.w;
    float ss = v.x * v.x + v.y * v.y + v.z * v.z + v.w * v.w;

    __shared__ float smS[8], smQ[8];
    #pragma unroll
    for (int o = 16; o; o >>= 1) {
        s  += __shfl_xor_sync(0xffffffffu, s,  o);
        ss += __shfl_xor_sync(0xffffffffu, ss, o);
    }
    if ((t & 31) == 0) { smS[t >> 5] = s; smQ[t >> 5] = ss; }
    __syncthreads();
    float tS = 0.f, tQ = 0.f;
    #pragma unroll
    for (int i = 0; i < 8; i++) { tS += smS[i]; tQ += smQ[i]; }

    const float mean = tS * (1.0f / FEATS);
    const float var  = tQ * (1.0f / FEATS) - mean * mean;
    const float rstd = rsqrtf(var + LN_EPS);

    float4 gg = reinterpret_cast<const float4*>(g)[t];
    float4 bb = reinterpret_cast<const float4*>(b)[t];
    __half2* po = reinterpret_cast<__half2*>(out + row * FEATS) + t * 2;
    po[0] = __floats2half2_rn((v.x - mean) * rstd * gg.x + bb.x,
                              (v.y - mean) * rstd * gg.y + bb.y);
    po[1] = __floats2half2_rn((v.z - mean) * rstd * gg.z + bb.z,
                              (v.w - mean) * rstd * gg.w + bb.w);
}

// ---------------------------------------------------------------------------
// FP16 NT GEMM: BM=BN=128, BK=64, 3-stage cp.async ring, SW128 swizzle.
// ---------------------------------------------------------------------------
template<int EPI, bool SPLIT, bool OUT_HALF>
__global__ void __launch_bounds__(256, 2)
h_gemm(const __half* __restrict__ A,
       const __half* __restrict__ B0, const __half* __restrict__ B1,
       const __half* __restrict__ B2,
       void* __restrict__ C0, void* __restrict__ C1, void* __restrict__ C2,
       const float* __restrict__ bias0, const float* __restrict__ bias1,
       const float* __restrict__ bias2,
       const float* __restrict__ res,
       int K, int lda, int ldb, int ldc) {
    constexpr int STAGE_B = 32768;
    extern __shared__ __half gsm[];
    const uint32_t smem = smem_u32(gsm);

    const __half* Bp; void* Cv; const float* bias; int n0;
    if (SPLIT) {
        const int w = blockIdx.x >> 3;
        n0   = (blockIdx.x & 7) * 128;
        Bp   = (w == 0) ? B0 : (w == 1) ? B1 : B2;
        Cv   = (w == 0) ? C0 : (w == 1) ? C1 : C2;
        bias = (w == 0) ? bias0 : (w == 1) ? bias1 : bias2;
    } else {
        Bp = B0; Cv = C0; bias = bias0;
        n0 = blockIdx.x * 128;
    }
    const int m0 = blockIdx.y * 128;

    const int tid  = threadIdx.x;
    const int wid  = tid >> 5;
    const int lane = tid & 31;
    const int wm   = wid >> 2;
    const int wn   = wid & 3;
    const int cr   = tid >> 3;
    const int cc   = tid & 7;
    const int lrow = lane & 15;
    const int lchk = lane >> 4;

    float acc[4][4][4];
    #pragma unroll
    for (int i = 0; i < 4; i++)
        #pragma unroll
        for (int j = 0; j < 4; j++)
            #pragma unroll
            for (int r = 0; r < 4; r++) acc[i][j][r] = 0.f;

    auto stage = [&](int buf, int k0) {
        const uint32_t base = smem + buf * STAGE_B;
        #pragma unroll
        for (int i = 0; i < 4; i++) {
            const int row = cr + i * 32;
            CP_ASYNC16(base + swz(row, cc),
                       A + (size_t)(m0 + row) * lda + k0 + cc * 8);
            CP_ASYNC16(base + 16384 + swz(row, cc),
                       Bp + (size_t)(n0 + row) * ldb + k0 + cc * 8);
        }
    };

    const int nk = K / 64;
    stage(0, 0);  CP_COMMIT();
    stage(1, 64); CP_COMMIT();

    int cur = 0;
    for (int it = 0; it < nk; it++) {
        CP_WAIT(1);
        __syncthreads();
        const uint32_t aB = smem + cur * STAGE_B;
        const uint32_t bB = aB + 16384;
        #pragma unroll
        for (int kk = 0; kk < 4; kk++) {
            uint32_t af[4][4], bf[2][4];
            #pragma unroll
            for (int mi = 0; mi < 4; mi++)
                ldsm_x4(af[mi], aB + swz(wm * 64 + mi * 16 + lrow,
                                         kk * 2 + lchk));
            #pragma unroll
            for (int pi = 0; pi < 2; pi++)
                ldsm_x4(bf[pi], bB + swz(wn * 32 + pi * 16 + lrow,
                                         kk * 2 + lchk));
            #pragma unroll
            for (int mi = 0; mi < 4; mi++)
                #pragma unroll
                for (int ni = 0; ni < 4; ni++) {
                    const int pi = ni >> 1, od = ni & 1;
                    mma_f16(acc[mi][ni], af[mi][0], af[mi][1], af[mi][2],
                            af[mi][3], bf[pi][od], bf[pi][od + 2]);
                }
        }
        if (it + 2 < nk) stage((cur + 2) % 3, (it + 2) * 64);
        CP_COMMIT();
        cur = (cur + 1) % 3;
    }

    const int lq = lane >> 2, lr = lane & 3;
    #pragma unroll
    for (int mi = 0; mi < 4; mi++) {
        #pragma unroll
        for (int ni = 0; ni < 4; ni++) {
            const int r = m0 + wm * 64 + mi * 16 + lq;
            const int c = n0 + wn * 32 + ni * 8 + lr * 2;
            float2 v0, v1;
            v0.x = acc[mi][ni][0]; v0.y = acc[mi][ni][1];
            v1.x = acc[mi][ni][2]; v1.y = acc[mi][ni][3];
            float2 b2 = *reinterpret_cast<const float2*>(&bias[c]);
            v0.x += b2.x; v0.y += b2.y;
            v1.x += b2.x; v1.y += b2.y;
            if (EPI == 1 || EPI == 3) {
                v0.x = fmaxf(v0.x, 0.f); v0.y = fmaxf(v0.y, 0.f);
                v1.x = fmaxf(v1.x, 0.f); v1.y = fmaxf(v1.y, 0.f);
            }
            if (EPI == 2 || EPI == 3) {
                float2 r0 = *reinterpret_cast<const float2*>(
                    &res[(size_t)r * ldc + c]);
                float2 r1 = *reinterpret_cast<const float2*>(
                    &res[(size_t)(r + 8) * ldc + c]);
                v0.x += r0.x; v0.y += r0.y;
                v1.x += r1.x; v1.y += r1.y;
            }
            if (OUT_HALF) {
                __half* Ch = (__half*)Cv;
                *reinterpret_cast<__half2*>(&Ch[(size_t)r * ldc + c]) =
                    __floats2half2_rn(v0.x, v0.y);
                *reinterpret_cast<__half2*>(&Ch[(size_t)(r + 8) * ldc + c]) =
                    __floats2half2_rn(v1.x, v1.y);
            } else {
                float* Cf = (float*)Cv;
                *reinterpret_cast<float2*>(&Cf[(size_t)r * ldc + c])       = v0;
                *reinterpret_cast<float2*>(&Cf[(size_t)(r + 8) * ldc + c]) = v1;
            }
        }
    }
}

// ---------------------------------------------------------------------------
// FP16 flash attention, chunked softmax (2 x 64-wide chunks per KV tile)
// -> sacc halved -> fits 128 regs -> 2 CTAs/SM (16 warps).
// smem 80KB: sQ + 2 x (sK + sV), SW128 swizzled.
// ---------------------------------------------------------------------------
__global__ void __launch_bounds__(256, 2)
flash_kernel(const __half* __restrict__ Q, const __half* __restrict__ K,
             const __half* __restrict__ V, __half* __restrict__ Out) {
    extern __shared__ __half fsm[];
    const uint32_t sQ = smem_u32(fsm);

    const int bh = blockIdx.y;
    const int bb = bh >> 4;
    const int hh = bh & 15;
    const int q0 = blockIdx.x * 128;
    const size_t base = (size_t)bb * SEQ * FEATS + (size_t)hh * HD;

    const int tid  = threadIdx.x;
    const int wid  = tid >> 5;
    const int lane = tid & 31;
    const int lq   = lane >> 2;
    const int lr   = lane & 3;
    const int lrow = lane & 15;
    const int lchk = lane >> 4;
    const int cr   = tid >> 3;
    const int cc   = tid & 7;
    const int vrow = (lane & 7) + ((lane >> 3) & 1) * 8;

    #pragma unroll
    for (int i = 0; i < 4; i++) {
        const int row = cr + i * 32;
        CP_ASYNC16(sQ + swz(row, cc),
                   Q + base + (size_t)(q0 + row) * FEATS + cc * 8);
    }
    CP_COMMIT();

    auto stageKV = [&](int buf, int kv0) {
        const uint32_t kb = sQ + 16384 + buf * 32768;
        #pragma unroll
        for (int i = 0; i < 4; i++) {
            const int row = cr + i * 32;
            CP_ASYNC16(kb + swz(row, cc),
                       K + base + (size_t)(kv0 + row) * FEATS + cc * 8);
            CP_ASYNC16(kb + 16384 + swz(row, cc),
                       V + base + (size_t)(kv0 + row) * FEATS + cc * 8);
        }
    };
    stageKV(0, 0);
    CP_COMMIT();

    float oacc[8][4];
    #pragma unroll
    for (int i = 0; i < 8; i++)
        #pragma unroll
        for (int r = 0; r < 4; r++) oacc[i][r] = 0.f;
    float m0 = -1e30f, m1 = -1e30f, l0 = 0.f, l1 = 0.f;

    for (int t = 0; t < SEQ / 128; t++) {
        __syncthreads();
        if (t + 1 < SEQ / 128) stageKV((t + 1) & 1, (t + 1) * 128);
        CP_COMMIT();
        CP_WAIT(1);
        __syncthreads();

        const uint32_t kB = sQ + 16384 + (t & 1) * 32768;
        const uint32_t vB = kB + 16384;

        #pragma unroll
        for (int ch = 0; ch < 2; ch++) {
            // ---- S chunk = Q K^T (warp: 16 x 64) ----
            float sacc[8][4];
            #pragma unroll
            for (int i = 0; i < 8; i++)
                #pragma unroll
                for (int r = 0; r < 4; r++) sacc[i][r] = 0.f;

            #pragma unroll
            for (int kk = 0; kk < 4; kk++) {
                uint32_t aq[4];
                ldsm_x4(aq, sQ + swz(wid * 16 + lrow, kk * 2 + lchk));
                #pragma unroll
                for (int pi = 0; pi < 4; pi++) {
                    uint32_t bk[4];
                    ldsm_x4(bk, kB + swz(ch * 64 + pi * 16 + lrow,
                                         kk * 2 + lchk));
                    mma_f16(sacc[2 * pi    ], aq[0], aq[1], aq[2], aq[3],
                            bk[0], bk[2]);
                    mma_f16(sacc[2 * pi + 1], aq[0], aq[1], aq[2], aq[3],
                            bk[1], bk[3]);
                }
            }

            // ---- scale + online softmax (chunk) ----
            float mt0 = -1e30f, mt1 = -1e30f;
            #pragma unroll
            for (int ni = 0; ni < 8; ni++) {
                sacc[ni][0] *= 0.03125f; sacc[ni][1] *= 0.03125f;
                sacc[ni][2] *= 0.03125f; sacc[ni][3] *= 0.03125f;
                mt0 = fmaxf(mt0, fmaxf(sacc[ni][0], sacc[ni][1]));
                mt1 = fmaxf(mt1, fmaxf(sacc[ni][2], sacc[ni][3]));
            }
            mt0 = fmaxf(mt0, __shfl_xor_sync(0xffffffffu, mt0, 1));
            mt0 = fmaxf(mt0, __shfl_xor_sync(0xffffffffu, mt0, 2));
            mt1 = fmaxf(mt1, __shfl_xor_sync(0xffffffffu, mt1, 1));
            mt1 = fmaxf(mt1, __shfl_xor_sync(0xffffffffu, mt1, 2));

            const float mn0 = fmaxf(m0, mt0), mn1 = fmaxf(m1, mt1);
            const float al0 = __expf(m0 - mn0), al1 = __expf(m1 - mn1);
            float s0 = 0.f, s1 = 0.f;
            #pragma unroll
            for (int ni = 0; ni < 8; ni++) {
                sacc[ni][0] = __expf(sacc[ni][0] - mn0);
                sacc[ni][1] = __expf(sacc[ni][1] - mn0);
                sacc[ni][2] = __expf(sacc[ni][2] - mn1);
                sacc[ni][3] = __expf(sacc[ni][3] - mn1);
                s0 += sacc[ni][0] + sacc[ni][1];
                s1 += sacc[ni][2] + sacc[ni][3];
            }
            s0 += __shfl_xor_sync(0xffffffffu, s0, 1);
            s0 += __shfl_xor_sync(0xffffffffu, s0, 2);
            s1 += __shfl_xor_sync(0xffffffffu, s1, 1);
            s1 += __shfl_xor_sync(0xffffffffu, s1, 2);
            l0 = l0 * al0 + s0; l1 = l1 * al1 + s1;
            m0 = mn0; m1 = mn1;
            #pragma unroll
            for (int oni = 0; oni < 8; oni++) {
                oacc[oni][0] *= al0; oacc[oni][1] *= al0;
                oacc[oni][2] *= al1; oacc[oni][3] *= al1;
            }

            // ---- O += P_chunk V_chunk (K = 64) ----
            #pragma unroll
            for (int kk = 0; kk < 4; kk++) {
                const uint32_t a0 = pack_h2(sacc[2 * kk][0], sacc[2 * kk][1]);
                const uint32_t a1 = pack_h2(sacc[2 * kk][2], sacc[2 * kk][3]);
                const uint32_t a2 = pack_h2(sacc[2 * kk + 1][0],
                                            sacc[2 * kk + 1][1]);
                const uint32_t a3 = pack_h2(sacc[2 * kk + 1][2],
                                            sacc[2 * kk + 1][3]);
                #pragma unroll
                for (int nb = 0; nb < 4; nb++) {
                    uint32_t bv[4];
                    ldsm_x4_t(bv, vB + swz(ch * 64 + kk * 16 + vrow,
                                           nb * 2 + lchk));
                    mma_f16(oacc[2 * nb    ], a0, a1, a2, a3, bv[0], bv[1]);
                    mma_f16(oacc[2 * nb + 1], a0, a1, a2, a3, bv[2], bv[3]);
                }
            }
        }
    }

    const float inv0 = __fdividef(1.f, l0);
    const float inv1 = __fdividef(1.f, l1);
    const int mrow = wid * 16 + lq;
    __half* o0 = Out + base + (size_t)(q0 + mrow) * FEATS;
    __half* o1 = o0 + (size_t)8 * FEATS;
    #pragma unroll
    for (int oni = 0; oni < 8; oni++) {
        const int c = oni * 8 + lr * 2;
        *reinterpret_cast<__half2*>(o0 + c) =
            __floats2half2_rn(oacc[oni][0] * inv0, oacc[oni][1] * inv0);
        *reinterpret_cast<__half2*>(o1 + c) =
            __floats2half2_rn(oacc[oni][2] * inv1, oacc[oni][3] * inv1);
    }
}

// ---------------------------------------------------------------------------
#define GEMM_SMEM  (3 * 32768)      // 98304 B
#define FLASH_SMEM (5 * 16384)      // 81920 B

extern "C" void kernel_launch(void* const* d_in, const int* in_sizes, int n_in,
                              void* d_out, int out_size) {
    (void)in_sizes; (void)n_in; (void)out_size;
    const float* x    = (const float*)d_in[0];
    const float* ln1g = (const float*)d_in[1];
    const float* ln1b = (const float*)d_in[2];
    const float* wq   = (const float*)d_in[3];
    const float* bq   = (const float*)d_in[4];
    const float* wk   = (const float*)d_in[5];
    const float* bk   = (const float*)d_in[6];
    const float* wv   = (const float*)d_in[7];
    const float* bv   = (const float*)d_in[8];
    const float* wo   = (const float*)d_in[9];
    const float* bo   = (const float*)d_in[10];
    const float* ln2g = (const float*)d_in[11];
    const float* ln2b = (const float*)d_in[12];
    const float* w1   = (const float*)d_in[13];
    const float* b1   = (const float*)d_in[14];
    const float* w2   = (const float*)d_in[15];
    const float* b2   = (const float*)d_in[16];
    float* out = (float*)d_out;

    __half *h1, *q, *k, *v, *att, *h2, *m1;
    __half *wqh, *wkh, *wvh, *woh, *w1h, *w2h;
    float *out1;
    cudaGetSymbolAddress((void**)&h1,   g_h1h);
    cudaGetSymbolAddress((void**)&q,    g_qh);
    cudaGetSymbolAddress((void**)&k,    g_kh);
    cudaGetSymbolAddress((void**)&v,    g_vh);
    cudaGetSymbolAddress((void**)&att,  g_atth);
    cudaGetSymbolAddress((void**)&out1, g_out1);
    cudaGetSymbolAddress((void**)&h2,   g_h2h);
    cudaGetSymbolAddress((void**)&m1,   g_m1h);
    cudaGetSymbolAddress((void**)&wqh,  g_wqh);
    cudaGetSymbolAddress((void**)&wkh,  g_wkh);
    cudaGetSymbolAddress((void**)&wvh,  g_wvh);
    cudaGetSymbolAddress((void**)&woh,  g_woh);
    cudaGetSymbolAddress((void**)&w1h,  g_w1h);
    cudaGetSymbolAddress((void**)&w2h,  g_w2h);

    cudaFuncSetAttribute(h_gemm<0,true,true>,   cudaFuncAttributeMaxDynamicSharedMemorySize, GEMM_SMEM);
    cudaFuncSetAttribute(h_gemm<2,false,false>, cudaFuncAttributeMaxDynamicSharedMemorySize, GEMM_SMEM);
    cudaFuncSetAttribute(h_gemm<1,false,true>,  cudaFuncAttributeMaxDynamicSharedMemorySize, GEMM_SMEM);
    cudaFuncSetAttribute(h_gemm<3,false,false>, cudaFuncAttributeMaxDynamicSharedMemorySize, GEMM_SMEM);
    cudaFuncSetAttribute(flash_kernel, cudaFuncAttributeMaxDynamicSharedMemorySize, FLASH_SMEM);

    // 0) fused weight conversion (one launch)
    cvt_all_kernel<<<3145728 / 256, 256>>>(wq, wk, wv, wo, w1, w2,
                                           wqh, wkh, wvh, woh, w1h, w2h);

    // 1) LN1 -> fp16
    ln_kernel<<<TOK, 256>>>(x, ln1g, ln1b, h1);

    // 2) fused Q/K/V projections (fp16 out)
    {
        dim3 grid(24, TOK / 128);
        h_gemm<0,true,true><<<grid, 256, GEMM_SMEM>>>(
            h1, wqh, wkh, wvh, q, k, v, bq, bk, bv, nullptr,
            FEATS, FEATS, FEATS, FEATS);
    }

    // 3) flash attention (fp16 out)
    {
        dim3 grid(SEQ / 128, BATCH * HEADS);
        flash_kernel<<<grid, 256, FLASH_SMEM>>>(q, k, v, att);
    }

    // 4) O projection + residual x -> out1 (fp32)
    {
        dim3 grid(FEATS / 128, TOK / 128);
        h_gemm<2,false,false><<<grid, 256, GEMM_SMEM>>>(
            att, woh, nullptr, nullptr, out1, nullptr, nullptr,
            bo, nullptr, nullptr, x, FEATS, FEATS, FEATS, FEATS);
    }

    // 5) LN2 -> fp16
    ln_kernel<<<TOK, 256>>>(out1, ln2g, ln2b, h2);

    // 6) MLP up: relu(h2 @ w1^T + b1) -> m1 (fp16)
    {
        dim3 grid(HIDDEN / 128, TOK / 128);
        h_gemm<1,false,true><<<grid, 256, GEMM_SMEM>>>(
            h2, w1h, nullptr, nullptr, m1, nullptr, nullptr,
            b1, nullptr, nullptr, nullptr, FEATS, FEATS, FEATS, HIDDEN);
    }

    // 7) MLP down: relu(m1 @ w2^T + b2) + out1 -> out (fp32)
    {
        dim3 grid(FEATS / 128, TOK / 128);
        h_gemm<3,false,false><<<grid, 256, GEMM_SMEM>>>(
            m1, w2h, nullptr, nullptr, out, nullptr, nullptr,
            b2, nullptr, nullptr, out1, HIDDEN, HIDDEN, HIDDEN, FEATS);
    }
}